// round 1
// baseline (speedup 1.0000x reference)
#include <cuda_runtime.h>
#include <math.h>

// ---------------------------------------------------------------------------
// downprompt: 3x think-loop (GCN,GCN,CN-MLP, prompt*x) + 3-layer ELU GCN +
// prompt attention + class prototypes + cosine softmax.
// Key simplification: gcn_weight1 = gcn_weight3 = 0  =>  e3 is never used.
// ---------------------------------------------------------------------------

#define DD   256
#define MAXN 20000
#define MAXM 2048
#define NC   10

__device__ float g_x[MAXN * DD];
__device__ float g_h[MAXN * DD];
__device__ float g_agg[MAXN * DD];
__device__ float g_e1[MAXN * DD];
__device__ float g_e2[MAXN * DD];
__device__ float g_deg[MAXN];
__device__ float g_dinv[MAXN];
__device__ float g_invdeg[MAXN];
__device__ float g_raw[MAXM * DD];
__device__ float g_sums[NC * DD + 32];   // counts live at offset NC*DD
__device__ float g_an[NC * DD];

__device__ __forceinline__ float warp_sum(float v) {
#pragma unroll
    for (int o = 16; o > 0; o >>= 1) v += __shfl_xor_sync(0xffffffffu, v, o);
    return v;
}

// ---------------------------------------------------------------------------
// SGEMM: C[N,256] = A[N,256] @ B[256,256]  (+ epilogue)
// EPI 0: plain.  EPI 1: elu(acc + bias).  EPI 2: (acc + bias) * extra[row,col]
// 64x64 tile, BK=16, 256 threads, 4x4 microtile.
// ---------------------------------------------------------------------------
template <int EPI>
__global__ void __launch_bounds__(256) sgemm_k256(
    const float* __restrict__ A, const float* __restrict__ B,
    const float* __restrict__ bias, const float* __restrict__ extra,
    float* __restrict__ C, int N)
{
    __shared__ __align__(16) float As[16][64];
    __shared__ __align__(16) float Bs[16][64];

    const int tid = threadIdx.x;
    const int tx = tid & 15;      // col group 0..15
    const int ty = tid >> 4;      // row group 0..15
    const int rowBase = blockIdx.x * 64;
    const int colBase = blockIdx.y * 64;

    // A load: one float4 per thread
    const int a_r = tid >> 2;           // 0..63
    const int a_k = (tid & 3) * 4;      // 0,4,8,12
    // B load: one float4 per thread
    const int b_k = tid >> 4;           // 0..15
    const int b_c = (tid & 15) * 4;     // 0..60

    float acc[4][4] = {};

    for (int k0 = 0; k0 < 256; k0 += 16) {
        int grow = rowBase + a_r;
        float4 av = make_float4(0.f, 0.f, 0.f, 0.f);
        if (grow < N) av = *(const float4*)(A + (size_t)grow * 256 + k0 + a_k);
        As[a_k + 0][a_r] = av.x;
        As[a_k + 1][a_r] = av.y;
        As[a_k + 2][a_r] = av.z;
        As[a_k + 3][a_r] = av.w;

        float4 bv = *(const float4*)(B + (size_t)(k0 + b_k) * 256 + colBase + b_c);
        *(float4*)&Bs[b_k][b_c] = bv;
        __syncthreads();

#pragma unroll
        for (int k = 0; k < 16; k++) {
            float4 a4 = *(const float4*)&As[k][ty * 4];
            float4 b4 = *(const float4*)&Bs[k][tx * 4];
            acc[0][0] += a4.x * b4.x; acc[0][1] += a4.x * b4.y;
            acc[0][2] += a4.x * b4.z; acc[0][3] += a4.x * b4.w;
            acc[1][0] += a4.y * b4.x; acc[1][1] += a4.y * b4.y;
            acc[1][2] += a4.y * b4.z; acc[1][3] += a4.y * b4.w;
            acc[2][0] += a4.z * b4.x; acc[2][1] += a4.z * b4.y;
            acc[2][2] += a4.z * b4.z; acc[2][3] += a4.z * b4.w;
            acc[3][0] += a4.w * b4.x; acc[3][1] += a4.w * b4.y;
            acc[3][2] += a4.w * b4.z; acc[3][3] += a4.w * b4.w;
        }
        __syncthreads();
    }

    const int col = colBase + tx * 4;
    float bx = 0.f, by = 0.f, bz = 0.f, bw = 0.f;
    if (EPI >= 1) { bx = bias[col]; by = bias[col + 1]; bz = bias[col + 2]; bw = bias[col + 3]; }

#pragma unroll
    for (int i = 0; i < 4; i++) {
        int row = rowBase + ty * 4 + i;
        if (row >= N) continue;
        float v0 = acc[i][0] + bx, v1 = acc[i][1] + by;
        float v2 = acc[i][2] + bz, v3 = acc[i][3] + bw;
        if (EPI == 1) {
            v0 = v0 > 0.f ? v0 : expm1f(v0);
            v1 = v1 > 0.f ? v1 : expm1f(v1);
            v2 = v2 > 0.f ? v2 : expm1f(v2);
            v3 = v3 > 0.f ? v3 : expm1f(v3);
        }
        if (EPI == 2) {
            float4 ex = *(const float4*)(extra + (size_t)row * 256 + col);
            v0 *= ex.x; v1 *= ex.y; v2 *= ex.z; v3 *= ex.w;
        }
        *(float4*)(C + (size_t)row * 256 + col) = make_float4(v0, v1, v2, v3);
    }
}

// ---------------------------------------------------------------------------
// Degree / normalization
// ---------------------------------------------------------------------------
__global__ void count_deg(const int* __restrict__ dst, float* __restrict__ deg, int E) {
    int e = blockIdx.x * blockDim.x + threadIdx.x;
    if (e < E) atomicAdd(&deg[dst[e]], 1.f);
}

__global__ void finalize_deg(const float* __restrict__ deg, float* __restrict__ dinv,
                             float* __restrict__ invdeg, int N) {
    int i = blockIdx.x * blockDim.x + threadIdx.x;
    if (i < N) {
        float d = deg[i] + 1.f;
        dinv[i] = rsqrtf(d);
        invdeg[i] = 1.f / d;
    }
}

// ---------------------------------------------------------------------------
// Edge scatter: agg[dst] += h[src] * dinv[src] * dinv[dst]   (1 warp / edge)
// ---------------------------------------------------------------------------
__global__ void __launch_bounds__(256) scatter_edges(
    const float* __restrict__ h, const int* __restrict__ src,
    const int* __restrict__ dst, const float* __restrict__ dinv,
    float* __restrict__ agg, int E)
{
    int w = (blockIdx.x * blockDim.x + threadIdx.x) >> 5;
    int lane = threadIdx.x & 31;
    if (w >= E) return;
    int s = src[w], d = dst[w];
    float c = dinv[s] * dinv[d];
    const float4* hr = (const float4*)(h + (size_t)s * DD);
    float* ar = agg + (size_t)d * DD;
#pragma unroll
    for (int i = 0; i < 2; i++) {
        float4 v = hr[lane + 32 * i];
        int b = (lane + 32 * i) * 4;
        atomicAdd(ar + b + 0, v.x * c);
        atomicAdd(ar + b + 1, v.y * c);
        atomicAdd(ar + b + 2, v.z * c);
        atomicAdd(ar + b + 3, v.w * c);
    }
}

// ---------------------------------------------------------------------------
// out = agg + h*invdeg[row] + bias[col]  (+res) (*scale) (elu)
// ---------------------------------------------------------------------------
template <int RES, int SCALE, int ELU>
__global__ void __launch_bounds__(256) gcn_combine(
    const float* __restrict__ agg, const float* __restrict__ h,
    const float* __restrict__ bias, const float* __restrict__ invdeg,
    const float* __restrict__ res, const float* __restrict__ scale_ptr,
    float* __restrict__ out, int N)
{
    size_t i = (size_t)blockIdx.x * blockDim.x + threadIdx.x;
    if (i >= (size_t)N * DD) return;
    int row = (int)(i >> 8);
    int col = (int)(i & 255);
    float v = agg[i] + h[i] * invdeg[row] + bias[col];
    if (RES) v += res[i];
    if (SCALE) v *= scale_ptr[0];
    if (ELU) v = v > 0.f ? v : expm1f(v);
    out[i] = v;
}

// ---------------------------------------------------------------------------
// Prompt attention, restricted to the M=2048 selected rows. 1 warp / row.
// raw[m] = h[i] + softmax(h[i]@aW + ab) @ p_list,  i = idx[m]
// ---------------------------------------------------------------------------
__global__ void __launch_bounds__(256) embed_select(
    const float* __restrict__ h, const float* __restrict__ aW,
    const float* __restrict__ ab, const float* __restrict__ p,
    const int* __restrict__ idx, float* __restrict__ raw, int M)
{
    int m = (blockIdx.x * blockDim.x + threadIdx.x) >> 5;
    int lane = threadIdx.x & 31;
    if (m >= M) return;
    int node = idx[m];
    const float* hr = h + (size_t)node * DD;
    float hv[8];
    float lg[5] = {0.f, 0.f, 0.f, 0.f, 0.f};
#pragma unroll
    for (int i = 0; i < 8; i++) {
        int c = lane + 32 * i;
        hv[i] = hr[c];
#pragma unroll
        for (int k = 0; k < 5; k++) lg[k] += hv[i] * aW[c * 5 + k];
    }
#pragma unroll
    for (int k = 0; k < 5; k++) lg[k] = warp_sum(lg[k]) + ab[k];
    float mx = lg[0];
#pragma unroll
    for (int k = 1; k < 5; k++) mx = fmaxf(mx, lg[k]);
    float wgt[5], s = 0.f;
#pragma unroll
    for (int k = 0; k < 5; k++) { wgt[k] = expf(lg[k] - mx); s += wgt[k]; }
    float inv = 1.f / s;
#pragma unroll
    for (int k = 0; k < 5; k++) wgt[k] *= inv;
#pragma unroll
    for (int i = 0; i < 8; i++) {
        int c = lane + 32 * i;
        float v = hv[i];
#pragma unroll
        for (int k = 0; k < 5; k++) v += wgt[k] * p[k * DD + c];
        raw[(size_t)m * DD + c] = v;
    }
}

// ---------------------------------------------------------------------------
// Class prototype accumulation (scatter-mean, train==1 path)
// ---------------------------------------------------------------------------
__global__ void __launch_bounds__(256) proto_accum(
    const float* __restrict__ raw, const int* __restrict__ labels,
    float* __restrict__ sums, float* __restrict__ cnt, int M)
{
    int m = (blockIdx.x * blockDim.x + threadIdx.x) >> 5;
    int lane = threadIdx.x & 31;
    if (m >= M) return;
    int lab = labels[m];
#pragma unroll
    for (int i = 0; i < 8; i++) {
        int c = lane + 32 * i;
        atomicAdd(&sums[lab * DD + c], raw[(size_t)m * DD + c]);
    }
    if (lane == 0) atomicAdd(&cnt[lab], 1.f);
}

__global__ void an_finalize(const float* __restrict__ sums,
                            const float* __restrict__ cnt, float* __restrict__ an)
{
    int c = blockIdx.x;
    int lane = threadIdx.x;
    float invc = 1.f / fmaxf(cnt[c], 1.f);
    float v[8];
    float ss = 0.f;
#pragma unroll
    for (int i = 0; i < 8; i++) {
        v[i] = sums[c * DD + lane + 32 * i] * invc;
        ss += v[i] * v[i];
    }
    ss = warp_sum(ss);
    float innorm = 1.f / fmaxf(sqrtf(ss), 1e-8f);
#pragma unroll
    for (int i = 0; i < 8; i++) an[c * DD + lane + 32 * i] = v[i] * innorm;
}

// ---------------------------------------------------------------------------
// ret = softmax over classes of cosine(raw[m], ave[c]).  1 warp / row.
// ---------------------------------------------------------------------------
__global__ void __launch_bounds__(256) cos_softmax(
    const float* __restrict__ raw, const float* __restrict__ an,
    float* __restrict__ out, int M)
{
    __shared__ float sAn[NC * DD];
    for (int i = threadIdx.x; i < NC * DD; i += 256) sAn[i] = an[i];
    __syncthreads();
    int m = (blockIdx.x * blockDim.x + threadIdx.x) >> 5;
    int lane = threadIdx.x & 31;
    if (m >= M) return;
    float rv[8];
    float ss = 0.f;
#pragma unroll
    for (int i = 0; i < 8; i++) {
        rv[i] = raw[(size_t)m * DD + lane + 32 * i];
        ss += rv[i] * rv[i];
    }
    ss = warp_sum(ss);
    float rinv = 1.f / fmaxf(sqrtf(ss), 1e-8f);
    float sim[NC];
#pragma unroll
    for (int c = 0; c < NC; c++) {
        float s = 0.f;
#pragma unroll
        for (int i = 0; i < 8; i++) s += rv[i] * sAn[c * DD + lane + 32 * i];
        sim[c] = warp_sum(s) * rinv;
    }
    if (lane == 0) {
        float mx = sim[0];
#pragma unroll
        for (int c = 1; c < NC; c++) mx = fmaxf(mx, sim[c]);
        float e[NC], s = 0.f;
#pragma unroll
        for (int c = 0; c < NC; c++) { e[c] = expf(sim[c] - mx); s += e[c]; }
        float inv = 1.f / s;
#pragma unroll
        for (int c = 0; c < NC; c++) out[(size_t)m * NC + c] = e[c] * inv;
    }
}

// ---------------------------------------------------------------------------
// Orchestration
// ---------------------------------------------------------------------------
extern "C" void kernel_launch(void* const* d_in, const int* in_sizes, int n_in,
                              void* d_out, int out_size)
{
    const float* x0     = (const float*)d_in[0];
    const int*   src    = (const int*)d_in[1];
    const int*   dst    = (const int*)d_in[2];
    const int*   idx    = (const int*)d_in[3];
    const int*   labels = (const int*)d_in[4];
    // d_in[5] = train (always 1)
    const float* W1 = (const float*)d_in[6];
    const float* b1 = (const float*)d_in[7];
    const float* W2 = (const float*)d_in[8];
    const float* b2 = (const float*)d_in[9];
    const float* W3 = (const float*)d_in[10];
    const float* b3 = (const float*)d_in[11];
    const float* cw_in  = (const float*)d_in[12];
    const float* cb_in  = (const float*)d_in[13];
    const float* cw_hid = (const float*)d_in[14];
    const float* cb_hid = (const float*)d_in[15];
    const float* cw_out = (const float*)d_in[16];
    const float* cb_out = (const float*)d_in[17];
    const float* p_list = (const float*)d_in[18];
    const float* aW     = (const float*)d_in[19];
    const float* ab     = (const float*)d_in[20];
    const float* gw2    = (const float*)d_in[21];

    const int N = in_sizes[0] / DD;
    const int E = in_sizes[1];
    const int M = in_sizes[3];
    float* out = (float*)d_out;

    float *bx, *bh, *bagg, *be1, *be2, *bdeg, *bdinv, *binvdeg, *braw, *bsums, *ban;
    cudaGetSymbolAddress((void**)&bx, g_x);
    cudaGetSymbolAddress((void**)&bh, g_h);
    cudaGetSymbolAddress((void**)&bagg, g_agg);
    cudaGetSymbolAddress((void**)&be1, g_e1);
    cudaGetSymbolAddress((void**)&be2, g_e2);
    cudaGetSymbolAddress((void**)&bdeg, g_deg);
    cudaGetSymbolAddress((void**)&bdinv, g_dinv);
    cudaGetSymbolAddress((void**)&binvdeg, g_invdeg);
    cudaGetSymbolAddress((void**)&braw, g_raw);
    cudaGetSymbolAddress((void**)&bsums, g_sums);
    cudaGetSymbolAddress((void**)&ban, g_an);
    float* bcnt = bsums + NC * DD;

    // --- degrees (dst-only, + self-loop) ---
    cudaMemsetAsync(bdeg, 0, (size_t)N * sizeof(float), 0);
    count_deg<<<(E + 255) / 256, 256>>>(dst, bdeg, E);
    finalize_deg<<<(N + 255) / 256, 256>>>(bdeg, bdinv, binvdeg, N);

    const dim3 gg((N + 63) / 64, 4);
    const int eltBlocks = (int)(((size_t)N * DD + 255) / 256);
    const int scatBlocks = (E + 7) / 8;
    const size_t aggBytes = (size_t)N * DD * sizeof(float);

    const float* cur = x0;
    for (int t = 0; t < 3; t++) {
        // e1 = gcn(x, W1, b1)
        sgemm_k256<0><<<gg, 256>>>(cur, W1, nullptr, nullptr, bh, N);
        cudaMemsetAsync(bagg, 0, aggBytes, 0);
        scatter_edges<<<scatBlocks, 256>>>(bh, src, dst, bdinv, bagg, E);
        gcn_combine<0, 0, 0><<<eltBlocks, 256>>>(bagg, bh, b1, binvdeg, nullptr, nullptr, be1, N);
        // e2s = gcn_weight2 * (gcn(e1, W2, b2) + e1)   [e3 is dead: w1=w3=0]
        sgemm_k256<0><<<gg, 256>>>(be1, W2, nullptr, nullptr, bh, N);
        cudaMemsetAsync(bagg, 0, aggBytes, 0);
        scatter_edges<<<scatBlocks, 256>>>(bh, src, dst, bdinv, bagg, E);
        gcn_combine<1, 1, 0><<<eltBlocks, 256>>>(bagg, bh, b2, binvdeg, be1, gw2, be2, N);
        // ConditionNet: elu -> elu -> linear, then x = prompt * origin_x
        sgemm_k256<1><<<gg, 256>>>(be2, cw_in + (size_t)t * DD * DD, cb_in + t * DD, nullptr, bh, N);
        sgemm_k256<1><<<gg, 256>>>(bh, cw_hid + (size_t)t * DD * DD, cb_hid + t * DD, nullptr, be1, N);
        sgemm_k256<2><<<gg, 256>>>(be1, cw_out + (size_t)t * DD * DD, cb_out + t * DD, x0, bx, N);
        cur = bx;
    }

    // --- final GCN with ELU between layers ---
    sgemm_k256<0><<<gg, 256>>>(bx, W1, nullptr, nullptr, bh, N);
    cudaMemsetAsync(bagg, 0, aggBytes, 0);
    scatter_edges<<<scatBlocks, 256>>>(bh, src, dst, bdinv, bagg, E);
    gcn_combine<0, 0, 1><<<eltBlocks, 256>>>(bagg, bh, b1, binvdeg, nullptr, nullptr, be1, N);

    sgemm_k256<0><<<gg, 256>>>(be1, W2, nullptr, nullptr, bh, N);
    cudaMemsetAsync(bagg, 0, aggBytes, 0);
    scatter_edges<<<scatBlocks, 256>>>(bh, src, dst, bdinv, bagg, E);
    gcn_combine<0, 0, 1><<<eltBlocks, 256>>>(bagg, bh, b2, binvdeg, nullptr, nullptr, be2, N);

    sgemm_k256<0><<<gg, 256>>>(be2, W3, nullptr, nullptr, bh, N);
    cudaMemsetAsync(bagg, 0, aggBytes, 0);
    scatter_edges<<<scatBlocks, 256>>>(bh, src, dst, bdinv, bagg, E);
    gcn_combine<0, 0, 1><<<eltBlocks, 256>>>(bagg, bh, b3, binvdeg, nullptr, nullptr, be1, N);

    // --- prompt attention on the selected rows only ---
    embed_select<<<(M + 7) / 8, 256>>>(be1, aW, ab, p_list, idx, braw, M);

    // --- prototypes + cosine softmax ---
    cudaMemsetAsync(bsums, 0, (NC * DD + 32) * sizeof(float), 0);
    proto_accum<<<(M + 7) / 8, 256>>>(braw, labels, bsums, bcnt, M);
    an_finalize<<<NC, 32>>>(bsums, bcnt, ban);
    cos_softmax<<<(M + 7) / 8, 256>>>(braw, ban, out, M);
}

// round 2
// speedup vs baseline: 1.9003x; 1.9003x over previous
#include <cuda_runtime.h>
#include <math.h>

// ---------------------------------------------------------------------------
// downprompt: 3x think-loop (GCN,GCN,CN-MLP, prompt*x) + 3-layer ELU GCN +
// prompt attention + class prototypes + cosine softmax.
// Simplifications: gcn_weight1 = gcn_weight3 = 0  =>  e3 is dead.
// R2: atomic scatter -> CSR gather SpMM with fused combine epilogue.
// ---------------------------------------------------------------------------

#define DD   256
#define MAXN 20000
#define MAXE 320000
#define MAXM 2048
#define NC   10

__device__ float g_x[MAXN * DD];
__device__ float g_h[MAXN * DD];
__device__ float g_e1[MAXN * DD];
__device__ float g_e2[MAXN * DD];
__device__ int   g_degi[MAXN];
__device__ float g_dinv[MAXN];
__device__ float g_invdeg[MAXN];
__device__ int   g_rowptr[MAXN + 1];
__device__ int   g_cursor[MAXN];
__device__ int   g_csrsrc[MAXE];
__device__ float g_coef[MAXE];
__device__ float g_raw[MAXM * DD];
__device__ float g_sums[NC * DD + 32];   // counts live at offset NC*DD
__device__ float g_an[NC * DD];

__device__ __forceinline__ float warp_sum(float v) {
#pragma unroll
    for (int o = 16; o > 0; o >>= 1) v += __shfl_xor_sync(0xffffffffu, v, o);
    return v;
}

// ---------------------------------------------------------------------------
// SGEMM: C[N,256] = A[N,256] @ B[256,256]  (+ epilogue)
// EPI 0: plain.  EPI 1: elu(acc + bias).  EPI 2: (acc + bias) * extra[row,col]
// ---------------------------------------------------------------------------
template <int EPI>
__global__ void __launch_bounds__(256) sgemm_k256(
    const float* __restrict__ A, const float* __restrict__ B,
    const float* __restrict__ bias, const float* __restrict__ extra,
    float* __restrict__ C, int N)
{
    __shared__ __align__(16) float As[16][64];
    __shared__ __align__(16) float Bs[16][64];

    const int tid = threadIdx.x;
    const int tx = tid & 15;
    const int ty = tid >> 4;
    const int rowBase = blockIdx.x * 64;
    const int colBase = blockIdx.y * 64;

    const int a_r = tid >> 2;
    const int a_k = (tid & 3) * 4;
    const int b_k = tid >> 4;
    const int b_c = (tid & 15) * 4;

    float acc[4][4] = {};

    for (int k0 = 0; k0 < 256; k0 += 16) {
        int grow = rowBase + a_r;
        float4 av = make_float4(0.f, 0.f, 0.f, 0.f);
        if (grow < N) av = *(const float4*)(A + (size_t)grow * 256 + k0 + a_k);
        As[a_k + 0][a_r] = av.x;
        As[a_k + 1][a_r] = av.y;
        As[a_k + 2][a_r] = av.z;
        As[a_k + 3][a_r] = av.w;

        float4 bv = *(const float4*)(B + (size_t)(k0 + b_k) * 256 + colBase + b_c);
        *(float4*)&Bs[b_k][b_c] = bv;
        __syncthreads();

#pragma unroll
        for (int k = 0; k < 16; k++) {
            float4 a4 = *(const float4*)&As[k][ty * 4];
            float4 b4 = *(const float4*)&Bs[k][tx * 4];
            acc[0][0] += a4.x * b4.x; acc[0][1] += a4.x * b4.y;
            acc[0][2] += a4.x * b4.z; acc[0][3] += a4.x * b4.w;
            acc[1][0] += a4.y * b4.x; acc[1][1] += a4.y * b4.y;
            acc[1][2] += a4.y * b4.z; acc[1][3] += a4.y * b4.w;
            acc[2][0] += a4.z * b4.x; acc[2][1] += a4.z * b4.y;
            acc[2][2] += a4.z * b4.z; acc[2][3] += a4.z * b4.w;
            acc[3][0] += a4.w * b4.x; acc[3][1] += a4.w * b4.y;
            acc[3][2] += a4.w * b4.z; acc[3][3] += a4.w * b4.w;
        }
        __syncthreads();
    }

    const int col = colBase + tx * 4;
    float bx = 0.f, by = 0.f, bz = 0.f, bw = 0.f;
    if (EPI >= 1) { bx = bias[col]; by = bias[col + 1]; bz = bias[col + 2]; bw = bias[col + 3]; }

#pragma unroll
    for (int i = 0; i < 4; i++) {
        int row = rowBase + ty * 4 + i;
        if (row >= N) continue;
        float v0 = acc[i][0] + bx, v1 = acc[i][1] + by;
        float v2 = acc[i][2] + bz, v3 = acc[i][3] + bw;
        if (EPI == 1) {
            v0 = v0 > 0.f ? v0 : expm1f(v0);
            v1 = v1 > 0.f ? v1 : expm1f(v1);
            v2 = v2 > 0.f ? v2 : expm1f(v2);
            v3 = v3 > 0.f ? v3 : expm1f(v3);
        }
        if (EPI == 2) {
            float4 ex = *(const float4*)(extra + (size_t)row * 256 + col);
            v0 *= ex.x; v1 *= ex.y; v2 *= ex.z; v3 *= ex.w;
        }
        *(float4*)(C + (size_t)row * 256 + col) = make_float4(v0, v1, v2, v3);
    }
}

// ---------------------------------------------------------------------------
// CSR build
// ---------------------------------------------------------------------------
__global__ void count_deg(const int* __restrict__ dst, int* __restrict__ degi, int E) {
    int e = blockIdx.x * blockDim.x + threadIdx.x;
    if (e < E) atomicAdd(&degi[dst[e]], 1);
}

__global__ void finalize_deg(const int* __restrict__ degi, float* __restrict__ dinv,
                             float* __restrict__ invdeg, int N) {
    int i = blockIdx.x * blockDim.x + threadIdx.x;
    if (i < N) {
        float d = (float)degi[i] + 1.f;
        dinv[i] = rsqrtf(d);
        invdeg[i] = 1.f / d;
    }
}

// Single-block exclusive scan of degi -> rowptr (N <= 20000).
__global__ void __launch_bounds__(1024) scan_rowptr(
    const int* __restrict__ degi, int* __restrict__ rowptr, int N)
{
    __shared__ int s[1024];
    const int t = threadIdx.x;
    const int per = (N + 1023) / 1024;
    const int beg = t * per;
    const int end = min(beg + per, N);
    int sum = 0;
    for (int i = beg; i < end; i++) sum += degi[i];
    s[t] = sum;
    __syncthreads();
#pragma unroll
    for (int off = 1; off < 1024; off <<= 1) {
        int v = (t >= off) ? s[t - off] : 0;
        __syncthreads();
        s[t] += v;
        __syncthreads();
    }
    int run = s[t] - sum;   // exclusive prefix for this thread's chunk
    for (int i = beg; i < end; i++) { rowptr[i] = run; run += degi[i]; }
    if (t == 1023) rowptr[N] = s[1023];
}

__global__ void fill_csr(const int* __restrict__ src, const int* __restrict__ dst,
                         const float* __restrict__ dinv,
                         const int* __restrict__ rowptr, int* __restrict__ cursor,
                         int* __restrict__ csrsrc, float* __restrict__ coef, int E)
{
    int e = blockIdx.x * blockDim.x + threadIdx.x;
    if (e >= E) return;
    int s = src[e], d = dst[e];
    int p = atomicAdd(&cursor[d], 1);
    int slot = rowptr[d] + p;
    csrsrc[slot] = s;
    coef[slot] = dinv[s] * dinv[d];
}

// ---------------------------------------------------------------------------
// Gather SpMM + fused combine.  1 warp per destination row.
// out[d] = sum_{e in row d} coef[e]*h[src[e]]  + h[d]*invdeg[d] + bias
//          (+res[d]) (*scale) (elu)
// ---------------------------------------------------------------------------
template <int RES, int SCALE, int ELU>
__global__ void __launch_bounds__(256) gather_gcn(
    const float* __restrict__ h, const int* __restrict__ rowptr,
    const int* __restrict__ csrsrc, const float* __restrict__ coef,
    const float* __restrict__ bias, const float* __restrict__ invdeg,
    const float* __restrict__ res, const float* __restrict__ scale_ptr,
    float* __restrict__ out, int N)
{
    int d = (blockIdx.x * blockDim.x + threadIdx.x) >> 5;
    int lane = threadIdx.x & 31;
    if (d >= N) return;

    const int eBeg = rowptr[d];
    const int eEnd = rowptr[d + 1];

    float4 acc0 = make_float4(0.f, 0.f, 0.f, 0.f);
    float4 acc1 = make_float4(0.f, 0.f, 0.f, 0.f);

    int e = eBeg;
    for (; e + 1 < eEnd; e += 2) {
        int s0 = csrsrc[e];     float c0 = coef[e];
        int s1 = csrsrc[e + 1]; float c1 = coef[e + 1];
        const float4* h0 = (const float4*)(h + (size_t)s0 * DD);
        const float4* h1 = (const float4*)(h + (size_t)s1 * DD);
        float4 v0a = h0[lane], v0b = h0[32 + lane];
        float4 v1a = h1[lane], v1b = h1[32 + lane];
        acc0.x += v0a.x * c0; acc0.y += v0a.y * c0; acc0.z += v0a.z * c0; acc0.w += v0a.w * c0;
        acc1.x += v0b.x * c0; acc1.y += v0b.y * c0; acc1.z += v0b.z * c0; acc1.w += v0b.w * c0;
        acc0.x += v1a.x * c1; acc0.y += v1a.y * c1; acc0.z += v1a.z * c1; acc0.w += v1a.w * c1;
        acc1.x += v1b.x * c1; acc1.y += v1b.y * c1; acc1.z += v1b.z * c1; acc1.w += v1b.w * c1;
    }
    if (e < eEnd) {
        int s0 = csrsrc[e]; float c0 = coef[e];
        const float4* h0 = (const float4*)(h + (size_t)s0 * DD);
        float4 v0a = h0[lane], v0b = h0[32 + lane];
        acc0.x += v0a.x * c0; acc0.y += v0a.y * c0; acc0.z += v0a.z * c0; acc0.w += v0a.w * c0;
        acc1.x += v0b.x * c0; acc1.y += v0b.y * c0; acc1.z += v0b.z * c0; acc1.w += v0b.w * c0;
    }

    // self-loop + bias
    const float idg = invdeg[d];
    const float4* hd = (const float4*)(h + (size_t)d * DD);
    float4 sa = hd[lane], sb = hd[32 + lane];
    const float4* bi = (const float4*)bias;
    float4 ba = bi[lane], bb = bi[32 + lane];
    acc0.x += sa.x * idg + ba.x; acc0.y += sa.y * idg + ba.y;
    acc0.z += sa.z * idg + ba.z; acc0.w += sa.w * idg + ba.w;
    acc1.x += sb.x * idg + bb.x; acc1.y += sb.y * idg + bb.y;
    acc1.z += sb.z * idg + bb.z; acc1.w += sb.w * idg + bb.w;

    if (RES) {
        const float4* rr = (const float4*)(res + (size_t)d * DD);
        float4 ra = rr[lane], rb = rr[32 + lane];
        acc0.x += ra.x; acc0.y += ra.y; acc0.z += ra.z; acc0.w += ra.w;
        acc1.x += rb.x; acc1.y += rb.y; acc1.z += rb.z; acc1.w += rb.w;
    }
    if (SCALE) {
        float sc = scale_ptr[0];
        acc0.x *= sc; acc0.y *= sc; acc0.z *= sc; acc0.w *= sc;
        acc1.x *= sc; acc1.y *= sc; acc1.z *= sc; acc1.w *= sc;
    }
    if (ELU) {
        acc0.x = acc0.x > 0.f ? acc0.x : expm1f(acc0.x);
        acc0.y = acc0.y > 0.f ? acc0.y : expm1f(acc0.y);
        acc0.z = acc0.z > 0.f ? acc0.z : expm1f(acc0.z);
        acc0.w = acc0.w > 0.f ? acc0.w : expm1f(acc0.w);
        acc1.x = acc1.x > 0.f ? acc1.x : expm1f(acc1.x);
        acc1.y = acc1.y > 0.f ? acc1.y : expm1f(acc1.y);
        acc1.z = acc1.z > 0.f ? acc1.z : expm1f(acc1.z);
        acc1.w = acc1.w > 0.f ? acc1.w : expm1f(acc1.w);
    }
    float4* orow = (float4*)(out + (size_t)d * DD);
    orow[lane] = acc0;
    orow[32 + lane] = acc1;
}

// ---------------------------------------------------------------------------
// Prompt attention on the M selected rows. 1 warp / row.
// ---------------------------------------------------------------------------
__global__ void __launch_bounds__(256) embed_select(
    const float* __restrict__ h, const float* __restrict__ aW,
    const float* __restrict__ ab, const float* __restrict__ p,
    const int* __restrict__ idx, float* __restrict__ raw, int M)
{
    int m = (blockIdx.x * blockDim.x + threadIdx.x) >> 5;
    int lane = threadIdx.x & 31;
    if (m >= M) return;
    int node = idx[m];
    const float* hr = h + (size_t)node * DD;
    float hv[8];
    float lg[5] = {0.f, 0.f, 0.f, 0.f, 0.f};
#pragma unroll
    for (int i = 0; i < 8; i++) {
        int c = lane + 32 * i;
        hv[i] = hr[c];
#pragma unroll
        for (int k = 0; k < 5; k++) lg[k] += hv[i] * aW[c * 5 + k];
    }
#pragma unroll
    for (int k = 0; k < 5; k++) lg[k] = warp_sum(lg[k]) + ab[k];
    float mx = lg[0];
#pragma unroll
    for (int k = 1; k < 5; k++) mx = fmaxf(mx, lg[k]);
    float wgt[5], s = 0.f;
#pragma unroll
    for (int k = 0; k < 5; k++) { wgt[k] = expf(lg[k] - mx); s += wgt[k]; }
    float inv = 1.f / s;
#pragma unroll
    for (int k = 0; k < 5; k++) wgt[k] *= inv;
#pragma unroll
    for (int i = 0; i < 8; i++) {
        int c = lane + 32 * i;
        float v = hv[i];
#pragma unroll
        for (int k = 0; k < 5; k++) v += wgt[k] * p[k * DD + c];
        raw[(size_t)m * DD + c] = v;
    }
}

// ---------------------------------------------------------------------------
// Class prototypes + cosine softmax
// ---------------------------------------------------------------------------
__global__ void __launch_bounds__(256) proto_accum(
    const float* __restrict__ raw, const int* __restrict__ labels,
    float* __restrict__ sums, float* __restrict__ cnt, int M)
{
    int m = (blockIdx.x * blockDim.x + threadIdx.x) >> 5;
    int lane = threadIdx.x & 31;
    if (m >= M) return;
    int lab = labels[m];
#pragma unroll
    for (int i = 0; i < 8; i++) {
        int c = lane + 32 * i;
        atomicAdd(&sums[lab * DD + c], raw[(size_t)m * DD + c]);
    }
    if (lane == 0) atomicAdd(&cnt[lab], 1.f);
}

__global__ void an_finalize(const float* __restrict__ sums,
                            const float* __restrict__ cnt, float* __restrict__ an)
{
    int c = blockIdx.x;
    int lane = threadIdx.x;
    float invc = 1.f / fmaxf(cnt[c], 1.f);
    float v[8];
    float ss = 0.f;
#pragma unroll
    for (int i = 0; i < 8; i++) {
        v[i] = sums[c * DD + lane + 32 * i] * invc;
        ss += v[i] * v[i];
    }
    ss = warp_sum(ss);
    float innorm = 1.f / fmaxf(sqrtf(ss), 1e-8f);
#pragma unroll
    for (int i = 0; i < 8; i++) an[c * DD + lane + 32 * i] = v[i] * innorm;
}

__global__ void __launch_bounds__(256) cos_softmax(
    const float* __restrict__ raw, const float* __restrict__ an,
    float* __restrict__ out, int M)
{
    __shared__ float sAn[NC * DD];
    for (int i = threadIdx.x; i < NC * DD; i += 256) sAn[i] = an[i];
    __syncthreads();
    int m = (blockIdx.x * blockDim.x + threadIdx.x) >> 5;
    int lane = threadIdx.x & 31;
    if (m >= M) return;
    float rv[8];
    float ss = 0.f;
#pragma unroll
    for (int i = 0; i < 8; i++) {
        rv[i] = raw[(size_t)m * DD + lane + 32 * i];
        ss += rv[i] * rv[i];
    }
    ss = warp_sum(ss);
    float rinv = 1.f / fmaxf(sqrtf(ss), 1e-8f);
    float sim[NC];
#pragma unroll
    for (int c = 0; c < NC; c++) {
        float s = 0.f;
#pragma unroll
        for (int i = 0; i < 8; i++) s += rv[i] * sAn[c * DD + lane + 32 * i];
        sim[c] = warp_sum(s) * rinv;
    }
    if (lane == 0) {
        float mx = sim[0];
#pragma unroll
        for (int c = 1; c < NC; c++) mx = fmaxf(mx, sim[c]);
        float e[NC], s = 0.f;
#pragma unroll
        for (int c = 0; c < NC; c++) { e[c] = expf(sim[c] - mx); s += e[c]; }
        float inv = 1.f / s;
#pragma unroll
        for (int c = 0; c < NC; c++) out[(size_t)m * NC + c] = e[c] * inv;
    }
}

// ---------------------------------------------------------------------------
// Orchestration
// ---------------------------------------------------------------------------
extern "C" void kernel_launch(void* const* d_in, const int* in_sizes, int n_in,
                              void* d_out, int out_size)
{
    const float* x0     = (const float*)d_in[0];
    const int*   src    = (const int*)d_in[1];
    const int*   dst    = (const int*)d_in[2];
    const int*   idx    = (const int*)d_in[3];
    const int*   labels = (const int*)d_in[4];
    const float* W1 = (const float*)d_in[6];
    const float* b1 = (const float*)d_in[7];
    const float* W2 = (const float*)d_in[8];
    const float* b2 = (const float*)d_in[9];
    const float* W3 = (const float*)d_in[10];
    const float* b3 = (const float*)d_in[11];
    const float* cw_in  = (const float*)d_in[12];
    const float* cb_in  = (const float*)d_in[13];
    const float* cw_hid = (const float*)d_in[14];
    const float* cb_hid = (const float*)d_in[15];
    const float* cw_out = (const float*)d_in[16];
    const float* cb_out = (const float*)d_in[17];
    const float* p_list = (const float*)d_in[18];
    const float* aW     = (const float*)d_in[19];
    const float* ab     = (const float*)d_in[20];
    const float* gw2    = (const float*)d_in[21];

    const int N = in_sizes[0] / DD;
    const int E = in_sizes[1];
    const int M = in_sizes[3];
    float* out = (float*)d_out;

    float *bx, *bh, *be1, *be2, *bdinv, *binvdeg, *braw, *bsums, *ban, *bcoef;
    int *bdegi, *browptr, *bcursor, *bcsrsrc;
    cudaGetSymbolAddress((void**)&bx, g_x);
    cudaGetSymbolAddress((void**)&bh, g_h);
    cudaGetSymbolAddress((void**)&be1, g_e1);
    cudaGetSymbolAddress((void**)&be2, g_e2);
    cudaGetSymbolAddress((void**)&bdegi, g_degi);
    cudaGetSymbolAddress((void**)&bdinv, g_dinv);
    cudaGetSymbolAddress((void**)&binvdeg, g_invdeg);
    cudaGetSymbolAddress((void**)&browptr, g_rowptr);
    cudaGetSymbolAddress((void**)&bcursor, g_cursor);
    cudaGetSymbolAddress((void**)&bcsrsrc, g_csrsrc);
    cudaGetSymbolAddress((void**)&bcoef, g_coef);
    cudaGetSymbolAddress((void**)&braw, g_raw);
    cudaGetSymbolAddress((void**)&bsums, g_sums);
    cudaGetSymbolAddress((void**)&ban, g_an);
    float* bcnt = bsums + NC * DD;

    // --- CSR build (once per call) ---
    cudaMemsetAsync(bdegi, 0, (size_t)N * sizeof(int), 0);
    cudaMemsetAsync(bcursor, 0, (size_t)N * sizeof(int), 0);
    count_deg<<<(E + 255) / 256, 256>>>(dst, bdegi, E);
    finalize_deg<<<(N + 255) / 256, 256>>>(bdegi, bdinv, binvdeg, N);
    scan_rowptr<<<1, 1024>>>(bdegi, browptr, N);
    fill_csr<<<(E + 255) / 256, 256>>>(src, dst, bdinv, browptr, bcursor, bcsrsrc, bcoef, E);

    const dim3 gg((N + 63) / 64, 4);
    const int rowBlocks = (N + 7) / 8;   // 8 warps/block, 1 warp/row

    const float* cur = x0;
    for (int t = 0; t < 3; t++) {
        // e1 = gcn(x, W1, b1)
        sgemm_k256<0><<<gg, 256>>>(cur, W1, nullptr, nullptr, bh, N);
        gather_gcn<0, 0, 0><<<rowBlocks, 256>>>(bh, browptr, bcsrsrc, bcoef, b1, binvdeg,
                                                nullptr, nullptr, be1, N);
        // e2s = gw2 * (gcn(e1, W2, b2) + e1)   [e3 dead: w1=w3=0]
        sgemm_k256<0><<<gg, 256>>>(be1, W2, nullptr, nullptr, bh, N);
        gather_gcn<1, 1, 0><<<rowBlocks, 256>>>(bh, browptr, bcsrsrc, bcoef, b2, binvdeg,
                                                be1, gw2, be2, N);
        // ConditionNet: elu -> elu -> linear, then x = prompt * origin_x
        sgemm_k256<1><<<gg, 256>>>(be2, cw_in + (size_t)t * DD * DD, cb_in + t * DD, nullptr, bh, N);
        sgemm_k256<1><<<gg, 256>>>(bh, cw_hid + (size_t)t * DD * DD, cb_hid + t * DD, nullptr, be1, N);
        sgemm_k256<2><<<gg, 256>>>(be1, cw_out + (size_t)t * DD * DD, cb_out + t * DD, x0, bx, N);
        cur = bx;
    }

    // --- final GCN with ELU ---
    sgemm_k256<0><<<gg, 256>>>(bx, W1, nullptr, nullptr, bh, N);
    gather_gcn<0, 0, 1><<<rowBlocks, 256>>>(bh, browptr, bcsrsrc, bcoef, b1, binvdeg,
                                            nullptr, nullptr, be1, N);
    sgemm_k256<0><<<gg, 256>>>(be1, W2, nullptr, nullptr, bh, N);
    gather_gcn<0, 0, 1><<<rowBlocks, 256>>>(bh, browptr, bcsrsrc, bcoef, b2, binvdeg,
                                            nullptr, nullptr, be2, N);
    sgemm_k256<0><<<gg, 256>>>(be2, W3, nullptr, nullptr, bh, N);
    gather_gcn<0, 0, 1><<<rowBlocks, 256>>>(bh, browptr, bcsrsrc, bcoef, b3, binvdeg,
                                            nullptr, nullptr, be1, N);

    // --- prompt attention on selected rows ---
    embed_select<<<(M + 7) / 8, 256>>>(be1, aW, ab, p_list, idx, braw, M);

    // --- prototypes + cosine softmax ---
    cudaMemsetAsync(bsums, 0, (NC * DD + 32) * sizeof(float), 0);
    proto_accum<<<(M + 7) / 8, 256>>>(braw, labels, bsums, bcnt, M);
    an_finalize<<<NC, 32>>>(bsums, bcnt, ban);
    cos_softmax<<<(M + 7) / 8, 256>>>(braw, ban, out, M);
}

// round 3
// speedup vs baseline: 3.6769x; 1.9349x over previous
#include <cuda_runtime.h>
#include <math.h>
#include <stdint.h>

// ---------------------------------------------------------------------------
// downprompt. R3: all 18 GEMMs moved to TF32 tensor cores (mma.sync m16n8k8).
// Pipeline: CSR-gather GCN aggregation (R2), dead-code e3 elimination (R1).
// ---------------------------------------------------------------------------

#define DD   256
#define MAXN 20000
#define MAXE 320000
#define MAXM 2048
#define NC   10

__device__ float g_x[MAXN * DD];
__device__ float g_h[MAXN * DD];
__device__ float g_e1[MAXN * DD];
__device__ float g_e2[MAXN * DD];
__device__ int   g_degi[MAXN];
__device__ float g_dinv[MAXN];
__device__ float g_invdeg[MAXN];
__device__ int   g_rowptr[MAXN + 1];
__device__ int   g_cursor[MAXN];
__device__ int   g_csrsrc[MAXE];
__device__ float g_coef[MAXE];
__device__ float g_raw[MAXM * DD];
__device__ float g_sums[NC * DD + 32];
__device__ float g_an[NC * DD];

__device__ __forceinline__ float warp_sum(float v) {
#pragma unroll
    for (int o = 16; o > 0; o >>= 1) v += __shfl_xor_sync(0xffffffffu, v, o);
    return v;
}

__device__ __forceinline__ uint32_t f2tf32(float f) {
    uint32_t u;
    asm("cvt.rna.tf32.f32 %0, %1;" : "=r"(u) : "f"(f));
    return u;
}

__device__ __forceinline__ void mma_tf32(
    float& c0, float& c1, float& c2, float& c3,
    uint32_t a0, uint32_t a1, uint32_t a2, uint32_t a3,
    uint32_t b0, uint32_t b1)
{
    asm volatile(
        "mma.sync.aligned.m16n8k8.row.col.f32.tf32.tf32.f32 "
        "{%0,%1,%2,%3},{%4,%5,%6,%7},{%8,%9},{%0,%1,%2,%3};"
        : "+f"(c0), "+f"(c1), "+f"(c2), "+f"(c3)
        : "r"(a0), "r"(a1), "r"(a2), "r"(a3), "r"(b0), "r"(b1));
}

// ---------------------------------------------------------------------------
// TF32 GEMM: C[N,256] = A[N,256] @ B[256,256]  (+ epilogue)
// EPI 0: plain. EPI 1: elu(acc+bias). EPI 2: (acc+bias)*extra[row,col]
// 128x128 tile, BK=32, 256 thr (8 warps 4Mx2N), warp tile 32x64.
// ---------------------------------------------------------------------------
#define APAD 4
#define BPAD 8
template <int EPI>
__global__ void __launch_bounds__(256) tf32_gemm(
    const float* __restrict__ A, const float* __restrict__ B,
    const float* __restrict__ bias, const float* __restrict__ extra,
    float* __restrict__ C, int N)
{
    __shared__ __align__(16) float As[128][32 + APAD];
    __shared__ __align__(16) float Bs[32][128 + BPAD];

    const int tid  = threadIdx.x;
    const int lane = tid & 31;
    const int wid  = tid >> 5;
    const int wm   = wid & 3;        // 0..3  (M)
    const int wn   = wid >> 2;       // 0..1  (N)
    const int rowBase = blockIdx.x * 128;
    const int colBase = blockIdx.y * 128;

    const int lq = lane >> 2;        // 0..7
    const int lr = lane & 3;         // 0..3

    float acc[2][8][4];
#pragma unroll
    for (int mt = 0; mt < 2; mt++)
#pragma unroll
        for (int nt = 0; nt < 8; nt++)
#pragma unroll
            for (int i = 0; i < 4; i++) acc[mt][nt][i] = 0.f;

    for (int k0 = 0; k0 < 256; k0 += 32) {
        // --- A tile: 128 rows x 32 k. 4 float4 per thread. ---
#pragma unroll
        for (int i = 0; i < 4; i++) {
            int f4 = tid + i * 256;
            int r  = f4 >> 3;            // 0..127
            int kc = (f4 & 7) * 4;       // 0..28
            int grow = rowBase + r;
            float4 v = make_float4(0.f, 0.f, 0.f, 0.f);
            if (grow < N) v = *(const float4*)(A + (size_t)grow * 256 + k0 + kc);
            As[r][kc + 0] = __uint_as_float(f2tf32(v.x));
            As[r][kc + 1] = __uint_as_float(f2tf32(v.y));
            As[r][kc + 2] = __uint_as_float(f2tf32(v.z));
            As[r][kc + 3] = __uint_as_float(f2tf32(v.w));
        }
        // --- B tile: 32 k x 128 cols. 4 float4 per thread. ---
#pragma unroll
        for (int i = 0; i < 4; i++) {
            int f4 = tid + i * 256;
            int kk = f4 >> 5;            // 0..31
            int nc = (f4 & 31) * 4;      // 0..124
            float4 v = *(const float4*)(B + (size_t)(k0 + kk) * 256 + colBase + nc);
            Bs[kk][nc + 0] = __uint_as_float(f2tf32(v.x));
            Bs[kk][nc + 1] = __uint_as_float(f2tf32(v.y));
            Bs[kk][nc + 2] = __uint_as_float(f2tf32(v.z));
            Bs[kk][nc + 3] = __uint_as_float(f2tf32(v.w));
        }
        __syncthreads();

#pragma unroll
        for (int kk = 0; kk < 32; kk += 8) {
            uint32_t a[2][4];
#pragma unroll
            for (int mt = 0; mt < 2; mt++) {
                int r = wm * 32 + mt * 16 + lq;
                a[mt][0] = __float_as_uint(As[r    ][kk + lr    ]);
                a[mt][1] = __float_as_uint(As[r + 8][kk + lr    ]);
                a[mt][2] = __float_as_uint(As[r    ][kk + lr + 4]);
                a[mt][3] = __float_as_uint(As[r + 8][kk + lr + 4]);
            }
            uint32_t b[8][2];
#pragma unroll
            for (int nt = 0; nt < 8; nt++) {
                int n = wn * 64 + nt * 8 + lq;
                b[nt][0] = __float_as_uint(Bs[kk + lr    ][n]);
                b[nt][1] = __float_as_uint(Bs[kk + lr + 4][n]);
            }
#pragma unroll
            for (int mt = 0; mt < 2; mt++)
#pragma unroll
                for (int nt = 0; nt < 8; nt++)
                    mma_tf32(acc[mt][nt][0], acc[mt][nt][1], acc[mt][nt][2], acc[mt][nt][3],
                             a[mt][0], a[mt][1], a[mt][2], a[mt][3],
                             b[nt][0], b[nt][1]);
        }
        __syncthreads();
    }

    // --- epilogue ---
#pragma unroll
    for (int mt = 0; mt < 2; mt++) {
#pragma unroll
        for (int rr = 0; rr < 2; rr++) {
            int row = rowBase + wm * 32 + mt * 16 + lq + rr * 8;
            if (row >= N) continue;
#pragma unroll
            for (int nt = 0; nt < 8; nt++) {
                int col = colBase + wn * 64 + nt * 8 + 2 * lr;
                float v0 = acc[mt][nt][rr * 2 + 0];
                float v1 = acc[mt][nt][rr * 2 + 1];
                if (EPI >= 1) { v0 += bias[col]; v1 += bias[col + 1]; }
                if (EPI == 1) {
                    v0 = v0 > 0.f ? v0 : expm1f(v0);
                    v1 = v1 > 0.f ? v1 : expm1f(v1);
                }
                if (EPI == 2) {
                    float2 ex = *(const float2*)(extra + (size_t)row * 256 + col);
                    v0 *= ex.x; v1 *= ex.y;
                }
                *(float2*)(C + (size_t)row * 256 + col) = make_float2(v0, v1);
            }
        }
    }
}

// ---------------------------------------------------------------------------
// CSR build
// ---------------------------------------------------------------------------
__global__ void count_deg(const int* __restrict__ dst, int* __restrict__ degi, int E) {
    int e = blockIdx.x * blockDim.x + threadIdx.x;
    if (e < E) atomicAdd(&degi[dst[e]], 1);
}

__global__ void finalize_deg(const int* __restrict__ degi, float* __restrict__ dinv,
                             float* __restrict__ invdeg, int N) {
    int i = blockIdx.x * blockDim.x + threadIdx.x;
    if (i < N) {
        float d = (float)degi[i] + 1.f;
        dinv[i] = rsqrtf(d);
        invdeg[i] = 1.f / d;
    }
}

__global__ void __launch_bounds__(1024) scan_rowptr(
    const int* __restrict__ degi, int* __restrict__ rowptr, int N)
{
    __shared__ int s[1024];
    const int t = threadIdx.x;
    const int per = (N + 1023) / 1024;
    const int beg = t * per;
    const int end = min(beg + per, N);
    int sum = 0;
    for (int i = beg; i < end; i++) sum += degi[i];
    s[t] = sum;
    __syncthreads();
#pragma unroll
    for (int off = 1; off < 1024; off <<= 1) {
        int v = (t >= off) ? s[t - off] : 0;
        __syncthreads();
        s[t] += v;
        __syncthreads();
    }
    int run = s[t] - sum;
    for (int i = beg; i < end; i++) { rowptr[i] = run; run += degi[i]; }
    if (t == 1023) rowptr[N] = s[1023];
}

__global__ void fill_csr(const int* __restrict__ src, const int* __restrict__ dst,
                         const float* __restrict__ dinv,
                         const int* __restrict__ rowptr, int* __restrict__ cursor,
                         int* __restrict__ csrsrc, float* __restrict__ coef, int E)
{
    int e = blockIdx.x * blockDim.x + threadIdx.x;
    if (e >= E) return;
    int s = src[e], d = dst[e];
    int p = atomicAdd(&cursor[d], 1);
    int slot = rowptr[d] + p;
    csrsrc[slot] = s;
    coef[slot] = dinv[s] * dinv[d];
}

// ---------------------------------------------------------------------------
// Gather SpMM + fused combine.  1 warp per destination row.
// ---------------------------------------------------------------------------
template <int RES, int SCALE, int ELU>
__global__ void __launch_bounds__(256) gather_gcn(
    const float* __restrict__ h, const int* __restrict__ rowptr,
    const int* __restrict__ csrsrc, const float* __restrict__ coef,
    const float* __restrict__ bias, const float* __restrict__ invdeg,
    const float* __restrict__ res, const float* __restrict__ scale_ptr,
    float* __restrict__ out, int N)
{
    int d = (blockIdx.x * blockDim.x + threadIdx.x) >> 5;
    int lane = threadIdx.x & 31;
    if (d >= N) return;

    const int eBeg = rowptr[d];
    const int eEnd = rowptr[d + 1];

    float4 acc0 = make_float4(0.f, 0.f, 0.f, 0.f);
    float4 acc1 = make_float4(0.f, 0.f, 0.f, 0.f);

    int e = eBeg;
    for (; e + 1 < eEnd; e += 2) {
        int s0 = csrsrc[e];     float c0 = coef[e];
        int s1 = csrsrc[e + 1]; float c1 = coef[e + 1];
        const float4* h0 = (const float4*)(h + (size_t)s0 * DD);
        const float4* h1 = (const float4*)(h + (size_t)s1 * DD);
        float4 v0a = h0[lane], v0b = h0[32 + lane];
        float4 v1a = h1[lane], v1b = h1[32 + lane];
        acc0.x += v0a.x * c0; acc0.y += v0a.y * c0; acc0.z += v0a.z * c0; acc0.w += v0a.w * c0;
        acc1.x += v0b.x * c0; acc1.y += v0b.y * c0; acc1.z += v0b.z * c0; acc1.w += v0b.w * c0;
        acc0.x += v1a.x * c1; acc0.y += v1a.y * c1; acc0.z += v1a.z * c1; acc0.w += v1a.w * c1;
        acc1.x += v1b.x * c1; acc1.y += v1b.y * c1; acc1.z += v1b.z * c1; acc1.w += v1b.w * c1;
    }
    if (e < eEnd) {
        int s0 = csrsrc[e]; float c0 = coef[e];
        const float4* h0 = (const float4*)(h + (size_t)s0 * DD);
        float4 v0a = h0[lane], v0b = h0[32 + lane];
        acc0.x += v0a.x * c0; acc0.y += v0a.y * c0; acc0.z += v0a.z * c0; acc0.w += v0a.w * c0;
        acc1.x += v0b.x * c0; acc1.y += v0b.y * c0; acc1.z += v0b.z * c0; acc1.w += v0b.w * c0;
    }

    const float idg = invdeg[d];
    const float4* hd = (const float4*)(h + (size_t)d * DD);
    float4 sa = hd[lane], sb = hd[32 + lane];
    const float4* bi = (const float4*)bias;
    float4 ba = bi[lane], bb = bi[32 + lane];
    acc0.x += sa.x * idg + ba.x; acc0.y += sa.y * idg + ba.y;
    acc0.z += sa.z * idg + ba.z; acc0.w += sa.w * idg + ba.w;
    acc1.x += sb.x * idg + bb.x; acc1.y += sb.y * idg + bb.y;
    acc1.z += sb.z * idg + bb.z; acc1.w += sb.w * idg + bb.w;

    if (RES) {
        const float4* rr = (const float4*)(res + (size_t)d * DD);
        float4 ra = rr[lane], rb = rr[32 + lane];
        acc0.x += ra.x; acc0.y += ra.y; acc0.z += ra.z; acc0.w += ra.w;
        acc1.x += rb.x; acc1.y += rb.y; acc1.z += rb.z; acc1.w += rb.w;
    }
    if (SCALE) {
        float sc = scale_ptr[0];
        acc0.x *= sc; acc0.y *= sc; acc0.z *= sc; acc0.w *= sc;
        acc1.x *= sc; acc1.y *= sc; acc1.z *= sc; acc1.w *= sc;
    }
    if (ELU) {
        acc0.x = acc0.x > 0.f ? acc0.x : expm1f(acc0.x);
        acc0.y = acc0.y > 0.f ? acc0.y : expm1f(acc0.y);
        acc0.z = acc0.z > 0.f ? acc0.z : expm1f(acc0.z);
        acc0.w = acc0.w > 0.f ? acc0.w : expm1f(acc0.w);
        acc1.x = acc1.x > 0.f ? acc1.x : expm1f(acc1.x);
        acc1.y = acc1.y > 0.f ? acc1.y : expm1f(acc1.y);
        acc1.z = acc1.z > 0.f ? acc1.z : expm1f(acc1.z);
        acc1.w = acc1.w > 0.f ? acc1.w : expm1f(acc1.w);
    }
    float4* orow = (float4*)(out + (size_t)d * DD);
    orow[lane] = acc0;
    orow[32 + lane] = acc1;
}

// ---------------------------------------------------------------------------
// Prompt attention on the M selected rows. 1 warp / row.
// ---------------------------------------------------------------------------
__global__ void __launch_bounds__(256) embed_select(
    const float* __restrict__ h, const float* __restrict__ aW,
    const float* __restrict__ ab, const float* __restrict__ p,
    const int* __restrict__ idx, float* __restrict__ raw, int M)
{
    int m = (blockIdx.x * blockDim.x + threadIdx.x) >> 5;
    int lane = threadIdx.x & 31;
    if (m >= M) return;
    int node = idx[m];
    const float* hr = h + (size_t)node * DD;
    float hv[8];
    float lg[5] = {0.f, 0.f, 0.f, 0.f, 0.f};
#pragma unroll
    for (int i = 0; i < 8; i++) {
        int c = lane + 32 * i;
        hv[i] = hr[c];
#pragma unroll
        for (int k = 0; k < 5; k++) lg[k] += hv[i] * aW[c * 5 + k];
    }
#pragma unroll
    for (int k = 0; k < 5; k++) lg[k] = warp_sum(lg[k]) + ab[k];
    float mx = lg[0];
#pragma unroll
    for (int k = 1; k < 5; k++) mx = fmaxf(mx, lg[k]);
    float wgt[5], s = 0.f;
#pragma unroll
    for (int k = 0; k < 5; k++) { wgt[k] = expf(lg[k] - mx); s += wgt[k]; }
    float inv = 1.f / s;
#pragma unroll
    for (int k = 0; k < 5; k++) wgt[k] *= inv;
#pragma unroll
    for (int i = 0; i < 8; i++) {
        int c = lane + 32 * i;
        float v = hv[i];
#pragma unroll
        for (int k = 0; k < 5; k++) v += wgt[k] * p[k * DD + c];
        raw[(size_t)m * DD + c] = v;
    }
}

// ---------------------------------------------------------------------------
// Class prototypes + cosine softmax
// ---------------------------------------------------------------------------
__global__ void __launch_bounds__(256) proto_accum(
    const float* __restrict__ raw, const int* __restrict__ labels,
    float* __restrict__ sums, float* __restrict__ cnt, int M)
{
    int m = (blockIdx.x * blockDim.x + threadIdx.x) >> 5;
    int lane = threadIdx.x & 31;
    if (m >= M) return;
    int lab = labels[m];
#pragma unroll
    for (int i = 0; i < 8; i++) {
        int c = lane + 32 * i;
        atomicAdd(&sums[lab * DD + c], raw[(size_t)m * DD + c]);
    }
    if (lane == 0) atomicAdd(&cnt[lab], 1.f);
}

__global__ void an_finalize(const float* __restrict__ sums,
                            const float* __restrict__ cnt, float* __restrict__ an)
{
    int c = blockIdx.x;
    int lane = threadIdx.x;
    float invc = 1.f / fmaxf(cnt[c], 1.f);
    float v[8];
    float ss = 0.f;
#pragma unroll
    for (int i = 0; i < 8; i++) {
        v[i] = sums[c * DD + lane + 32 * i] * invc;
        ss += v[i] * v[i];
    }
    ss = warp_sum(ss);
    float innorm = 1.f / fmaxf(sqrtf(ss), 1e-8f);
#pragma unroll
    for (int i = 0; i < 8; i++) an[c * DD + lane + 32 * i] = v[i] * innorm;
}

__global__ void __launch_bounds__(256) cos_softmax(
    const float* __restrict__ raw, const float* __restrict__ an,
    float* __restrict__ out, int M)
{
    __shared__ float sAn[NC * DD];
    for (int i = threadIdx.x; i < NC * DD; i += 256) sAn[i] = an[i];
    __syncthreads();
    int m = (blockIdx.x * blockDim.x + threadIdx.x) >> 5;
    int lane = threadIdx.x & 31;
    if (m >= M) return;
    float rv[8];
    float ss = 0.f;
#pragma unroll
    for (int i = 0; i < 8; i++) {
        rv[i] = raw[(size_t)m * DD + lane + 32 * i];
        ss += rv[i] * rv[i];
    }
    ss = warp_sum(ss);
    float rinv = 1.f / fmaxf(sqrtf(ss), 1e-8f);
    float sim[NC];
#pragma unroll
    for (int c = 0; c < NC; c++) {
        float s = 0.f;
#pragma unroll
        for (int i = 0; i < 8; i++) s += rv[i] * sAn[c * DD + lane + 32 * i];
        sim[c] = warp_sum(s) * rinv;
    }
    if (lane == 0) {
        float mx = sim[0];
#pragma unroll
        for (int c = 1; c < NC; c++) mx = fmaxf(mx, sim[c]);
        float e[NC], s = 0.f;
#pragma unroll
        for (int c = 0; c < NC; c++) { e[c] = expf(sim[c] - mx); s += e[c]; }
        float inv = 1.f / s;
#pragma unroll
        for (int c = 0; c < NC; c++) out[(size_t)m * NC + c] = e[c] * inv;
    }
}

// ---------------------------------------------------------------------------
// Orchestration
// ---------------------------------------------------------------------------
extern "C" void kernel_launch(void* const* d_in, const int* in_sizes, int n_in,
                              void* d_out, int out_size)
{
    const float* x0     = (const float*)d_in[0];
    const int*   src    = (const int*)d_in[1];
    const int*   dst    = (const int*)d_in[2];
    const int*   idx    = (const int*)d_in[3];
    const int*   labels = (const int*)d_in[4];
    const float* W1 = (const float*)d_in[6];
    const float* b1 = (const float*)d_in[7];
    const float* W2 = (const float*)d_in[8];
    const float* b2 = (const float*)d_in[9];
    const float* W3 = (const float*)d_in[10];
    const float* b3 = (const float*)d_in[11];
    const float* cw_in  = (const float*)d_in[12];
    const float* cb_in  = (const float*)d_in[13];
    const float* cw_hid = (const float*)d_in[14];
    const float* cb_hid = (const float*)d_in[15];
    const float* cw_out = (const float*)d_in[16];
    const float* cb_out = (const float*)d_in[17];
    const float* p_list = (const float*)d_in[18];
    const float* aW     = (const float*)d_in[19];
    const float* ab     = (const float*)d_in[20];
    const float* gw2    = (const float*)d_in[21];

    const int N = in_sizes[0] / DD;
    const int E = in_sizes[1];
    const int M = in_sizes[3];
    float* out = (float*)d_out;

    float *bx, *bh, *be1, *be2, *bdinv, *binvdeg, *braw, *bsums, *ban, *bcoef;
    int *bdegi, *browptr, *bcursor, *bcsrsrc;
    cudaGetSymbolAddress((void**)&bx, g_x);
    cudaGetSymbolAddress((void**)&bh, g_h);
    cudaGetSymbolAddress((void**)&be1, g_e1);
    cudaGetSymbolAddress((void**)&be2, g_e2);
    cudaGetSymbolAddress((void**)&bdegi, g_degi);
    cudaGetSymbolAddress((void**)&bdinv, g_dinv);
    cudaGetSymbolAddress((void**)&binvdeg, g_invdeg);
    cudaGetSymbolAddress((void**)&browptr, g_rowptr);
    cudaGetSymbolAddress((void**)&bcursor, g_cursor);
    cudaGetSymbolAddress((void**)&bcsrsrc, g_csrsrc);
    cudaGetSymbolAddress((void**)&bcoef, g_coef);
    cudaGetSymbolAddress((void**)&braw, g_raw);
    cudaGetSymbolAddress((void**)&bsums, g_sums);
    cudaGetSymbolAddress((void**)&ban, g_an);
    float* bcnt = bsums + NC * DD;

    // --- CSR build ---
    cudaMemsetAsync(bdegi, 0, (size_t)N * sizeof(int), 0);
    cudaMemsetAsync(bcursor, 0, (size_t)N * sizeof(int), 0);
    count_deg<<<(E + 255) / 256, 256>>>(dst, bdegi, E);
    finalize_deg<<<(N + 255) / 256, 256>>>(bdegi, bdinv, binvdeg, N);
    scan_rowptr<<<1, 1024>>>(bdegi, browptr, N);
    fill_csr<<<(E + 255) / 256, 256>>>(src, dst, bdinv, browptr, bcursor, bcsrsrc, bcoef, E);

    const dim3 gg((N + 127) / 128, 2);
    const int rowBlocks = (N + 7) / 8;

    const float* cur = x0;
    for (int t = 0; t < 3; t++) {
        tf32_gemm<0><<<gg, 256>>>(cur, W1, nullptr, nullptr, bh, N);
        gather_gcn<0, 0, 0><<<rowBlocks, 256>>>(bh, browptr, bcsrsrc, bcoef, b1, binvdeg,
                                                nullptr, nullptr, be1, N);
        tf32_gemm<0><<<gg, 256>>>(be1, W2, nullptr, nullptr, bh, N);
        gather_gcn<1, 1, 0><<<rowBlocks, 256>>>(bh, browptr, bcsrsrc, bcoef, b2, binvdeg,
                                                be1, gw2, be2, N);
        tf32_gemm<1><<<gg, 256>>>(be2, cw_in + (size_t)t * DD * DD, cb_in + t * DD, nullptr, bh, N);
        tf32_gemm<1><<<gg, 256>>>(bh, cw_hid + (size_t)t * DD * DD, cb_hid + t * DD, nullptr, be1, N);
        tf32_gemm<2><<<gg, 256>>>(be1, cw_out + (size_t)t * DD * DD, cb_out + t * DD, x0, bx, N);
        cur = bx;
    }

    tf32_gemm<0><<<gg, 256>>>(bx, W1, nullptr, nullptr, bh, N);
    gather_gcn<0, 0, 1><<<rowBlocks, 256>>>(bh, browptr, bcsrsrc, bcoef, b1, binvdeg,
                                            nullptr, nullptr, be1, N);
    tf32_gemm<0><<<gg, 256>>>(be1, W2, nullptr, nullptr, bh, N);
    gather_gcn<0, 0, 1><<<rowBlocks, 256>>>(bh, browptr, bcsrsrc, bcoef, b2, binvdeg,
                                            nullptr, nullptr, be2, N);
    tf32_gemm<0><<<gg, 256>>>(be2, W3, nullptr, nullptr, bh, N);
    gather_gcn<0, 0, 1><<<rowBlocks, 256>>>(bh, browptr, bcsrsrc, bcoef, b3, binvdeg,
                                            nullptr, nullptr, be1, N);

    embed_select<<<(M + 7) / 8, 256>>>(be1, aW, ab, p_list, idx, braw, M);

    cudaMemsetAsync(bsums, 0, (NC * DD + 32) * sizeof(float), 0);
    proto_accum<<<(M + 7) / 8, 256>>>(braw, labels, bsums, bcnt, M);
    an_finalize<<<NC, 32>>>(bsums, bcnt, ban);
    cos_softmax<<<(M + 7) / 8, 256>>>(braw, ban, out, M);
}

// round 4
// speedup vs baseline: 4.2734x; 1.1622x over previous
#include <cuda_runtime.h>
#include <cuda_bf16.h>
#include <math.h>
#include <stdint.h>

// ---------------------------------------------------------------------------
// downprompt. R4: cp.async double-buffered TF32 GEMM + bf16 gather path.
// Pipeline: CSR-gather aggregation (R2), dead-code e3 elimination (R1).
// ---------------------------------------------------------------------------

#define DD   256
#define MAXN 20000
#define MAXE 320000
#define MAXM 2048
#define NC   10

__device__ float g_x[MAXN * DD];
__device__ float g_h[MAXN * DD];                 // fp32 CN intermediate
__device__ __nv_bfloat16 g_hb[MAXN * DD];        // bf16 gather input
__device__ float g_e1[MAXN * DD];
__device__ float g_e2[MAXN * DD];
__device__ int   g_degi[MAXN];
__device__ float g_dinv[MAXN];
__device__ float g_invdeg[MAXN];
__device__ int   g_rowptr[MAXN + 1];
__device__ int   g_cursor[MAXN];
__device__ int   g_csrsrc[MAXE];
__device__ float g_coef[MAXE];
__device__ float g_raw[MAXM * DD];
__device__ float g_sums[NC * DD + 32];
__device__ float g_an[NC * DD];

__device__ __forceinline__ float warp_sum(float v) {
#pragma unroll
    for (int o = 16; o > 0; o >>= 1) v += __shfl_xor_sync(0xffffffffu, v, o);
    return v;
}

__device__ __forceinline__ void mma_tf32(
    float& c0, float& c1, float& c2, float& c3,
    uint32_t a0, uint32_t a1, uint32_t a2, uint32_t a3,
    uint32_t b0, uint32_t b1)
{
    asm volatile(
        "mma.sync.aligned.m16n8k8.row.col.f32.tf32.tf32.f32 "
        "{%0,%1,%2,%3},{%4,%5,%6,%7},{%8,%9},{%0,%1,%2,%3};"
        : "+f"(c0), "+f"(c1), "+f"(c2), "+f"(c3)
        : "r"(a0), "r"(a1), "r"(a2), "r"(a3), "r"(b0), "r"(b1));
}

__device__ __forceinline__ void cp_async16(void* smem_dst, const void* gmem_src, int src_bytes) {
    uint32_t s = (uint32_t)__cvta_generic_to_shared(smem_dst);
    asm volatile("cp.async.cg.shared.global [%0], [%1], 16, %2;"
                 :: "r"(s), "l"(gmem_src), "r"(src_bytes));
}

// ---------------------------------------------------------------------------
// TF32 GEMM: C[N,256] = A[N,256] @ B[256,256]  (+ epilogue)
// EPI 0: plain. EPI 1: elu(acc+bias). EPI 2: (acc+bias)*extra[row,col]
// BF16OUT: emit __nv_bfloat16 C (gather input), else fp32.
// 128x128 tile, BK=32, 2-stage cp.async pipeline, 8 warps (4Mx2N).
// Raw fp32 bits fed to tf32 mma (HW truncates mantissa).
// ---------------------------------------------------------------------------
#define AS_STRIDE 36   // 32 + 4 pad, 16B-aligned rows
#define BS_STRIDE 136  // 128 + 8 pad, 16B-aligned rows, conflict-free frags
#define AS_ELEMS (128 * AS_STRIDE)
#define BS_ELEMS (32 * BS_STRIDE)
#define GEMM_SMEM ((2 * AS_ELEMS + 2 * BS_ELEMS) * 4)

template <int EPI, int BF16OUT>
__global__ void __launch_bounds__(256) tf32_gemm(
    const float* __restrict__ A, const float* __restrict__ B,
    const float* __restrict__ bias, const float* __restrict__ extra,
    void* __restrict__ Cv, int N)
{
    extern __shared__ float sm[];
    float* AsBase = sm;
    float* BsBase = sm + 2 * AS_ELEMS;

    const int tid  = threadIdx.x;
    const int lane = tid & 31;
    const int wid  = tid >> 5;
    const int wm   = wid & 3;
    const int wn   = wid >> 2;
    const int rowBase = blockIdx.x * 128;
    const int colBase = blockIdx.y * 128;
    const int lq = lane >> 2;
    const int lr = lane & 3;

    float acc[2][8][4];
#pragma unroll
    for (int mt = 0; mt < 2; mt++)
#pragma unroll
        for (int nt = 0; nt < 8; nt++)
#pragma unroll
            for (int i = 0; i < 4; i++) acc[mt][nt][i] = 0.f;

    // tile loader (async)
    auto loadTile = [&](int k0, int stage) {
        float* As_ = AsBase + stage * AS_ELEMS;
        float* Bs_ = BsBase + stage * BS_ELEMS;
#pragma unroll
        for (int i = 0; i < 4; i++) {
            int f4 = tid + i * 256;
            int r = f4 >> 3, kc = (f4 & 7) * 4;
            int grow = rowBase + r;
            int ok = (grow < N) ? 16 : 0;
            int crow = grow < N ? grow : (N - 1);
            cp_async16(As_ + r * AS_STRIDE + kc, A + (size_t)crow * 256 + k0 + kc, ok);
        }
#pragma unroll
        for (int i = 0; i < 4; i++) {
            int f4 = tid + i * 256;
            int kk = f4 >> 5, nc = (f4 & 31) * 4;
            cp_async16(Bs_ + kk * BS_STRIDE + nc, B + (size_t)(k0 + kk) * 256 + colBase + nc, 16);
        }
        asm volatile("cp.async.commit_group;");
    };

    loadTile(0, 0);
#pragma unroll
    for (int it = 0; it < 8; it++) {
        if (it < 7) {
            loadTile((it + 1) * 32, (it + 1) & 1);
            asm volatile("cp.async.wait_group 1;");
        } else {
            asm volatile("cp.async.wait_group 0;");
        }
        __syncthreads();
        const float* As_ = AsBase + (it & 1) * AS_ELEMS;
        const float* Bs_ = BsBase + (it & 1) * BS_ELEMS;
#pragma unroll
        for (int kk = 0; kk < 32; kk += 8) {
            uint32_t a[2][4];
#pragma unroll
            for (int mt = 0; mt < 2; mt++) {
                int r = wm * 32 + mt * 16 + lq;
                a[mt][0] = __float_as_uint(As_[(r    ) * AS_STRIDE + kk + lr    ]);
                a[mt][1] = __float_as_uint(As_[(r + 8) * AS_STRIDE + kk + lr    ]);
                a[mt][2] = __float_as_uint(As_[(r    ) * AS_STRIDE + kk + lr + 4]);
                a[mt][3] = __float_as_uint(As_[(r + 8) * AS_STRIDE + kk + lr + 4]);
            }
            uint32_t b[8][2];
#pragma unroll
            for (int nt = 0; nt < 8; nt++) {
                int n = wn * 64 + nt * 8 + lq;
                b[nt][0] = __float_as_uint(Bs_[(kk + lr    ) * BS_STRIDE + n]);
                b[nt][1] = __float_as_uint(Bs_[(kk + lr + 4) * BS_STRIDE + n]);
            }
#pragma unroll
            for (int mt = 0; mt < 2; mt++)
#pragma unroll
                for (int nt = 0; nt < 8; nt++)
                    mma_tf32(acc[mt][nt][0], acc[mt][nt][1], acc[mt][nt][2], acc[mt][nt][3],
                             a[mt][0], a[mt][1], a[mt][2], a[mt][3],
                             b[nt][0], b[nt][1]);
        }
        __syncthreads();
    }

    // --- epilogue ---
#pragma unroll
    for (int mt = 0; mt < 2; mt++) {
#pragma unroll
        for (int rr = 0; rr < 2; rr++) {
            int row = rowBase + wm * 32 + mt * 16 + lq + rr * 8;
            if (row >= N) continue;
#pragma unroll
            for (int nt = 0; nt < 8; nt++) {
                int col = colBase + wn * 64 + nt * 8 + 2 * lr;
                float v0 = acc[mt][nt][rr * 2 + 0];
                float v1 = acc[mt][nt][rr * 2 + 1];
                if (EPI >= 1) { v0 += bias[col]; v1 += bias[col + 1]; }
                if (EPI == 1) {
                    v0 = v0 > 0.f ? v0 : expm1f(v0);
                    v1 = v1 > 0.f ? v1 : expm1f(v1);
                }
                if (EPI == 2) {
                    float2 ex = *(const float2*)(extra + (size_t)row * 256 + col);
                    v0 *= ex.x; v1 *= ex.y;
                }
                if (BF16OUT) {
                    __nv_bfloat162 h2 = __float22bfloat162_rn(make_float2(v0, v1));
                    *(__nv_bfloat162*)((__nv_bfloat16*)Cv + (size_t)row * 256 + col) = h2;
                } else {
                    *(float2*)((float*)Cv + (size_t)row * 256 + col) = make_float2(v0, v1);
                }
            }
        }
    }
}

// ---------------------------------------------------------------------------
// CSR build
// ---------------------------------------------------------------------------
__global__ void count_deg(const int* __restrict__ dst, int* __restrict__ degi, int E) {
    int e = blockIdx.x * blockDim.x + threadIdx.x;
    if (e < E) atomicAdd(&degi[dst[e]], 1);
}

__global__ void finalize_deg(const int* __restrict__ degi, float* __restrict__ dinv,
                             float* __restrict__ invdeg, int N) {
    int i = blockIdx.x * blockDim.x + threadIdx.x;
    if (i < N) {
        float d = (float)degi[i] + 1.f;
        dinv[i] = rsqrtf(d);
        invdeg[i] = 1.f / d;
    }
}

__global__ void __launch_bounds__(1024) scan_rowptr(
    const int* __restrict__ degi, int* __restrict__ rowptr, int N)
{
    __shared__ int s[1024];
    const int t = threadIdx.x;
    const int per = (N + 1023) / 1024;
    const int beg = t * per;
    const int end = min(beg + per, N);
    int sum = 0;
    for (int i = beg; i < end; i++) sum += degi[i];
    s[t] = sum;
    __syncthreads();
#pragma unroll
    for (int off = 1; off < 1024; off <<= 1) {
        int v = (t >= off) ? s[t - off] : 0;
        __syncthreads();
        s[t] += v;
        __syncthreads();
    }
    int run = s[t] - sum;
    for (int i = beg; i < end; i++) { rowptr[i] = run; run += degi[i]; }
    if (t == 1023) rowptr[N] = s[1023];
}

__global__ void fill_csr(const int* __restrict__ src, const int* __restrict__ dst,
                         const float* __restrict__ dinv,
                         const int* __restrict__ rowptr, int* __restrict__ cursor,
                         int* __restrict__ csrsrc, float* __restrict__ coef, int E)
{
    int e = blockIdx.x * blockDim.x + threadIdx.x;
    if (e >= E) return;
    int s = src[e], d = dst[e];
    int p = atomicAdd(&cursor[d], 1);
    int slot = rowptr[d] + p;
    csrsrc[slot] = s;
    coef[slot] = dinv[s] * dinv[d];
}

// ---------------------------------------------------------------------------
// Gather SpMM (bf16 h) + fused combine.  1 warp per destination row.
// out(fp32)[d] = sum coef*h[src] + h[d]*invdeg[d] + bias (+res)(*scale)(elu)
// ---------------------------------------------------------------------------
__device__ __forceinline__ void accum8(float* acc, uint4 v, float c) {
    __nv_bfloat162* p = (__nv_bfloat162*)&v;
#pragma unroll
    for (int j = 0; j < 4; j++) {
        float2 f = __bfloat1622float2(p[j]);
        acc[2 * j]     += f.x * c;
        acc[2 * j + 1] += f.y * c;
    }
}

template <int RES, int SCALE, int ELU>
__global__ void __launch_bounds__(256) gather_gcn_bf16(
    const __nv_bfloat16* __restrict__ h, const int* __restrict__ rowptr,
    const int* __restrict__ csrsrc, const float* __restrict__ coef,
    const float* __restrict__ bias, const float* __restrict__ invdeg,
    const float* __restrict__ res, const float* __restrict__ scale_ptr,
    float* __restrict__ out, int N)
{
    int d = (blockIdx.x * blockDim.x + threadIdx.x) >> 5;
    int lane = threadIdx.x & 31;
    if (d >= N) return;

    const int eBeg = rowptr[d];
    const int eEnd = rowptr[d + 1];
    const int coff = lane * 8;   // bf16 column base for this lane

    float acc[8] = {0.f, 0.f, 0.f, 0.f, 0.f, 0.f, 0.f, 0.f};

    int e = eBeg;
    for (; e + 1 < eEnd; e += 2) {
        int s0 = csrsrc[e];     float c0 = coef[e];
        int s1 = csrsrc[e + 1]; float c1 = coef[e + 1];
        uint4 v0 = *(const uint4*)(h + (size_t)s0 * DD + coff);
        uint4 v1 = *(const uint4*)(h + (size_t)s1 * DD + coff);
        accum8(acc, v0, c0);
        accum8(acc, v1, c1);
    }
    if (e < eEnd) {
        int s0 = csrsrc[e]; float c0 = coef[e];
        uint4 v0 = *(const uint4*)(h + (size_t)s0 * DD + coff);
        accum8(acc, v0, c0);
    }

    // self-loop + bias
    uint4 vs = *(const uint4*)(h + (size_t)d * DD + coff);
    accum8(acc, vs, invdeg[d]);
    float4 b0 = ((const float4*)bias)[lane * 2];
    float4 b1 = ((const float4*)bias)[lane * 2 + 1];
    acc[0] += b0.x; acc[1] += b0.y; acc[2] += b0.z; acc[3] += b0.w;
    acc[4] += b1.x; acc[5] += b1.y; acc[6] += b1.z; acc[7] += b1.w;

    if (RES) {
        float4 r0 = ((const float4*)(res + (size_t)d * DD))[lane * 2];
        float4 r1 = ((const float4*)(res + (size_t)d * DD))[lane * 2 + 1];
        acc[0] += r0.x; acc[1] += r0.y; acc[2] += r0.z; acc[3] += r0.w;
        acc[4] += r1.x; acc[5] += r1.y; acc[6] += r1.z; acc[7] += r1.w;
    }
    if (SCALE) {
        float sc = scale_ptr[0];
#pragma unroll
        for (int j = 0; j < 8; j++) acc[j] *= sc;
    }
    if (ELU) {
#pragma unroll
        for (int j = 0; j < 8; j++) acc[j] = acc[j] > 0.f ? acc[j] : expm1f(acc[j]);
    }
    float4* orow = (float4*)(out + (size_t)d * DD);
    orow[lane * 2]     = make_float4(acc[0], acc[1], acc[2], acc[3]);
    orow[lane * 2 + 1] = make_float4(acc[4], acc[5], acc[6], acc[7]);
}

// ---------------------------------------------------------------------------
// Prompt attention on the M selected rows. 1 warp / row.
// ---------------------------------------------------------------------------
__global__ void __launch_bounds__(256) embed_select(
    const float* __restrict__ h, const float* __restrict__ aW,
    const float* __restrict__ ab, const float* __restrict__ p,
    const int* __restrict__ idx, float* __restrict__ raw, int M)
{
    int m = (blockIdx.x * blockDim.x + threadIdx.x) >> 5;
    int lane = threadIdx.x & 31;
    if (m >= M) return;
    int node = idx[m];
    const float* hr = h + (size_t)node * DD;
    float hv[8];
    float lg[5] = {0.f, 0.f, 0.f, 0.f, 0.f};
#pragma unroll
    for (int i = 0; i < 8; i++) {
        int c = lane + 32 * i;
        hv[i] = hr[c];
#pragma unroll
        for (int k = 0; k < 5; k++) lg[k] += hv[i] * aW[c * 5 + k];
    }
#pragma unroll
    for (int k = 0; k < 5; k++) lg[k] = warp_sum(lg[k]) + ab[k];
    float mx = lg[0];
#pragma unroll
    for (int k = 1; k < 5; k++) mx = fmaxf(mx, lg[k]);
    float wgt[5], s = 0.f;
#pragma unroll
    for (int k = 0; k < 5; k++) { wgt[k] = expf(lg[k] - mx); s += wgt[k]; }
    float inv = 1.f / s;
#pragma unroll
    for (int k = 0; k < 5; k++) wgt[k] *= inv;
#pragma unroll
    for (int i = 0; i < 8; i++) {
        int c = lane + 32 * i;
        float v = hv[i];
#pragma unroll
        for (int k = 0; k < 5; k++) v += wgt[k] * p[k * DD + c];
        raw[(size_t)m * DD + c] = v;
    }
}

// ---------------------------------------------------------------------------
// Class prototypes + cosine softmax
// ---------------------------------------------------------------------------
__global__ void __launch_bounds__(256) proto_accum(
    const float* __restrict__ raw, const int* __restrict__ labels,
    float* __restrict__ sums, float* __restrict__ cnt, int M)
{
    int m = (blockIdx.x * blockDim.x + threadIdx.x) >> 5;
    int lane = threadIdx.x & 31;
    if (m >= M) return;
    int lab = labels[m];
#pragma unroll
    for (int i = 0; i < 8; i++) {
        int c = lane + 32 * i;
        atomicAdd(&sums[lab * DD + c], raw[(size_t)m * DD + c]);
    }
    if (lane == 0) atomicAdd(&cnt[lab], 1.f);
}

__global__ void an_finalize(const float* __restrict__ sums,
                            const float* __restrict__ cnt, float* __restrict__ an)
{
    int c = blockIdx.x;
    int lane = threadIdx.x;
    float invc = 1.f / fmaxf(cnt[c], 1.f);
    float v[8];
    float ss = 0.f;
#pragma unroll
    for (int i = 0; i < 8; i++) {
        v[i] = sums[c * DD + lane + 32 * i] * invc;
        ss += v[i] * v[i];
    }
    ss = warp_sum(ss);
    float innorm = 1.f / fmaxf(sqrtf(ss), 1e-8f);
#pragma unroll
    for (int i = 0; i < 8; i++) an[c * DD + lane + 32 * i] = v[i] * innorm;
}

__global__ void __launch_bounds__(256) cos_softmax(
    const float* __restrict__ raw, const float* __restrict__ an,
    float* __restrict__ out, int M)
{
    __shared__ float sAn[NC * DD];
    for (int i = threadIdx.x; i < NC * DD; i += 256) sAn[i] = an[i];
    __syncthreads();
    int m = (blockIdx.x * blockDim.x + threadIdx.x) >> 5;
    int lane = threadIdx.x & 31;
    if (m >= M) return;
    float rv[8];
    float ss = 0.f;
#pragma unroll
    for (int i = 0; i < 8; i++) {
        rv[i] = raw[(size_t)m * DD + lane + 32 * i];
        ss += rv[i] * rv[i];
    }
    ss = warp_sum(ss);
    float rinv = 1.f / fmaxf(sqrtf(ss), 1e-8f);
    float sim[NC];
#pragma unroll
    for (int c = 0; c < NC; c++) {
        float s = 0.f;
#pragma unroll
        for (int i = 0; i < 8; i++) s += rv[i] * sAn[c * DD + lane + 32 * i];
        sim[c] = warp_sum(s) * rinv;
    }
    if (lane == 0) {
        float mx = sim[0];
#pragma unroll
        for (int c = 1; c < NC; c++) mx = fmaxf(mx, sim[c]);
        float e[NC], s = 0.f;
#pragma unroll
        for (int c = 0; c < NC; c++) { e[c] = expf(sim[c] - mx); s += e[c]; }
        float inv = 1.f / s;
#pragma unroll
        for (int c = 0; c < NC; c++) out[(size_t)m * NC + c] = e[c] * inv;
    }
}

// ---------------------------------------------------------------------------
// Orchestration
// ---------------------------------------------------------------------------
extern "C" void kernel_launch(void* const* d_in, const int* in_sizes, int n_in,
                              void* d_out, int out_size)
{
    const float* x0     = (const float*)d_in[0];
    const int*   src    = (const int*)d_in[1];
    const int*   dst    = (const int*)d_in[2];
    const int*   idx    = (const int*)d_in[3];
    const int*   labels = (const int*)d_in[4];
    const float* W1 = (const float*)d_in[6];
    const float* b1 = (const float*)d_in[7];
    const float* W2 = (const float*)d_in[8];
    const float* b2 = (const float*)d_in[9];
    const float* W3 = (const float*)d_in[10];
    const float* b3 = (const float*)d_in[11];
    const float* cw_in  = (const float*)d_in[12];
    const float* cb_in  = (const float*)d_in[13];
    const float* cw_hid = (const float*)d_in[14];
    const float* cb_hid = (const float*)d_in[15];
    const float* cw_out = (const float*)d_in[16];
    const float* cb_out = (const float*)d_in[17];
    const float* p_list = (const float*)d_in[18];
    const float* aW     = (const float*)d_in[19];
    const float* ab     = (const float*)d_in[20];
    const float* gw2    = (const float*)d_in[21];

    const int N = in_sizes[0] / DD;
    const int E = in_sizes[1];
    const int M = in_sizes[3];
    float* out = (float*)d_out;

    float *bx, *bh, *be1, *be2, *bdinv, *binvdeg, *braw, *bsums, *ban, *bcoef;
    __nv_bfloat16* bhb;
    int *bdegi, *browptr, *bcursor, *bcsrsrc;
    cudaGetSymbolAddress((void**)&bx, g_x);
    cudaGetSymbolAddress((void**)&bh, g_h);
    cudaGetSymbolAddress((void**)&bhb, g_hb);
    cudaGetSymbolAddress((void**)&be1, g_e1);
    cudaGetSymbolAddress((void**)&be2, g_e2);
    cudaGetSymbolAddress((void**)&bdegi, g_degi);
    cudaGetSymbolAddress((void**)&bdinv, g_dinv);
    cudaGetSymbolAddress((void**)&binvdeg, g_invdeg);
    cudaGetSymbolAddress((void**)&browptr, g_rowptr);
    cudaGetSymbolAddress((void**)&bcursor, g_cursor);
    cudaGetSymbolAddress((void**)&bcsrsrc, g_csrsrc);
    cudaGetSymbolAddress((void**)&bcoef, g_coef);
    cudaGetSymbolAddress((void**)&braw, g_raw);
    cudaGetSymbolAddress((void**)&bsums, g_sums);
    cudaGetSymbolAddress((void**)&ban, g_an);
    float* bcnt = bsums + NC * DD;

    // raise dynamic smem limit for the GEMM instantiations (idempotent)
    cudaFuncSetAttribute(tf32_gemm<0, 1>, cudaFuncAttributeMaxDynamicSharedMemorySize, GEMM_SMEM);
    cudaFuncSetAttribute(tf32_gemm<1, 0>, cudaFuncAttributeMaxDynamicSharedMemorySize, GEMM_SMEM);
    cudaFuncSetAttribute(tf32_gemm<2, 0>, cudaFuncAttributeMaxDynamicSharedMemorySize, GEMM_SMEM);

    // --- CSR build ---
    cudaMemsetAsync(bdegi, 0, (size_t)N * sizeof(int), 0);
    cudaMemsetAsync(bcursor, 0, (size_t)N * sizeof(int), 0);
    count_deg<<<(E + 255) / 256, 256>>>(dst, bdegi, E);
    finalize_deg<<<(N + 255) / 256, 256>>>(bdegi, bdinv, binvdeg, N);
    scan_rowptr<<<1, 1024>>>(bdegi, browptr, N);
    fill_csr<<<(E + 255) / 256, 256>>>(src, dst, bdinv, browptr, bcursor, bcsrsrc, bcoef, E);

    const dim3 gg((N + 127) / 128, 2);
    const int rowBlocks = (N + 7) / 8;

    const float* cur = x0;
    for (int t = 0; t < 3; t++) {
        tf32_gemm<0, 1><<<gg, 256, GEMM_SMEM>>>(cur, W1, nullptr, nullptr, bhb, N);
        gather_gcn_bf16<0, 0, 0><<<rowBlocks, 256>>>(bhb, browptr, bcsrsrc, bcoef, b1, binvdeg,
                                                     nullptr, nullptr, be1, N);
        tf32_gemm<0, 1><<<gg, 256, GEMM_SMEM>>>(be1, W2, nullptr, nullptr, bhb, N);
        gather_gcn_bf16<1, 1, 0><<<rowBlocks, 256>>>(bhb, browptr, bcsrsrc, bcoef, b2, binvdeg,
                                                     be1, gw2, be2, N);
        tf32_gemm<1, 0><<<gg, 256, GEMM_SMEM>>>(be2, cw_in + (size_t)t * DD * DD, cb_in + t * DD,
                                                nullptr, bh, N);
        tf32_gemm<1, 0><<<gg, 256, GEMM_SMEM>>>(bh, cw_hid + (size_t)t * DD * DD, cb_hid + t * DD,
                                                nullptr, be1, N);
        tf32_gemm<2, 0><<<gg, 256, GEMM_SMEM>>>(be1, cw_out + (size_t)t * DD * DD, cb_out + t * DD,
                                                x0, bx, N);
        cur = bx;
    }

    tf32_gemm<0, 1><<<gg, 256, GEMM_SMEM>>>(bx, W1, nullptr, nullptr, bhb, N);
    gather_gcn_bf16<0, 0, 1><<<rowBlocks, 256>>>(bhb, browptr, bcsrsrc, bcoef, b1, binvdeg,
                                                 nullptr, nullptr, be1, N);
    tf32_gemm<0, 1><<<gg, 256, GEMM_SMEM>>>(be1, W2, nullptr, nullptr, bhb, N);
    gather_gcn_bf16<0, 0, 1><<<rowBlocks, 256>>>(bhb, browptr, bcsrsrc, bcoef, b2, binvdeg,
                                                 nullptr, nullptr, be2, N);
    tf32_gemm<0, 1><<<gg, 256, GEMM_SMEM>>>(be2, W3, nullptr, nullptr, bhb, N);
    gather_gcn_bf16<0, 0, 1><<<rowBlocks, 256>>>(bhb, browptr, bcsrsrc, bcoef, b3, binvdeg,
                                                 nullptr, nullptr, be1, N);

    embed_select<<<(M + 7) / 8, 256>>>(be1, aW, ab, p_list, idx, braw, M);

    cudaMemsetAsync(bsums, 0, (NC * DD + 32) * sizeof(float), 0);
    proto_accum<<<(M + 7) / 8, 256>>>(braw, labels, bsums, bcnt, M);
    an_finalize<<<NC, 32>>>(bsums, bcnt, ban);
    cos_softmax<<<(M + 7) / 8, 256>>>(braw, ban, out, M);
}

// round 5
// speedup vs baseline: 5.7583x; 1.3475x over previous
#include <cuda_runtime.h>
#include <cuda_bf16.h>
#include <math.h>
#include <stdint.h>

// ---------------------------------------------------------------------------
// downprompt. R5: full bf16 pipeline — HMMA m16n8k16 GEMMs with per-call
// weight prepack, bf16 activations everywhere, bf16 in/out CSR gather.
// Structure: dead-e3 elimination (R1), CSR gather (R2), cp.async (R4).
// ---------------------------------------------------------------------------

#define DD   256
#define MAXN 20000
#define MAXE 320000
#define MAXM 2048
#define NC   10

typedef __nv_bfloat16 bf16;
typedef __nv_bfloat162 bf162;

__device__ bf16  g_xb [MAXN * DD];   // current x (think loop)
__device__ bf16  g_x0b[MAXN * DD];   // origin x (bf16)
__device__ bf16  g_hb [MAXN * DD];   // GEMM out / CN hidden
__device__ bf16  g_e1b[MAXN * DD];
__device__ bf16  g_e2b[MAXN * DD];
__device__ uint32_t g_wp[12 * 32768];  // 12 prepacked weights [k2][n] k-pair uint32
__device__ int   g_degi[MAXN];
__device__ float g_dinv[MAXN];
__device__ float g_invdeg[MAXN];
__device__ int   g_rowptr[MAXN + 1];
__device__ int   g_cursor[MAXN];
__device__ int   g_csrsrc[MAXE];
__device__ float g_coef[MAXE];
__device__ float g_raw[MAXM * DD];
__device__ float g_sums[NC * DD + 32];
__device__ float g_an[NC * DD];

__device__ __forceinline__ float warp_sum(float v) {
#pragma unroll
    for (int o = 16; o > 0; o >>= 1) v += __shfl_xor_sync(0xffffffffu, v, o);
    return v;
}

__device__ __forceinline__ void mma_bf16(
    float& c0, float& c1, float& c2, float& c3,
    uint32_t a0, uint32_t a1, uint32_t a2, uint32_t a3,
    uint32_t b0, uint32_t b1)
{
    asm volatile(
        "mma.sync.aligned.m16n8k16.row.col.f32.bf16.bf16.f32 "
        "{%0,%1,%2,%3},{%4,%5,%6,%7},{%8,%9},{%0,%1,%2,%3};"
        : "+f"(c0), "+f"(c1), "+f"(c2), "+f"(c3)
        : "r"(a0), "r"(a1), "r"(a2), "r"(a3), "r"(b0), "r"(b1));
}

__device__ __forceinline__ void cp_async16(void* smem_dst, const void* gmem_src, int src_bytes) {
    uint32_t s = (uint32_t)__cvta_generic_to_shared(smem_dst);
    asm volatile("cp.async.cg.shared.global [%0], [%1], 16, %2;"
                 :: "r"(s), "l"(gmem_src), "r"(src_bytes));
}

// ---------------------------------------------------------------------------
// Weight prepack: Wp[m][k2*256+n] = (bf16(W[2k2][n]), bf16(W[2k2+1][n]))
// m: 0..2 = W1..W3, 3..5 = cw_in[t], 6..8 = cw_hid[t], 9..11 = cw_out[t]
// ---------------------------------------------------------------------------
__global__ void __launch_bounds__(256) prepack_weights(
    const float* __restrict__ W1, const float* __restrict__ W2,
    const float* __restrict__ W3, const float* __restrict__ cw_in,
    const float* __restrict__ cw_hid, const float* __restrict__ cw_out,
    uint32_t* __restrict__ wp)
{
    int m = blockIdx.y;
    const float* W =
        (m == 0) ? W1 : (m == 1) ? W2 : (m == 2) ? W3 :
        (m < 6) ? cw_in  + (size_t)(m - 3) * 65536 :
        (m < 9) ? cw_hid + (size_t)(m - 6) * 65536 :
                  cw_out + (size_t)(m - 9) * 65536;
    int i = blockIdx.x * 256 + threadIdx.x;      // k2*256 + n
    int k2 = i >> 8, n = i & 255;
    float lo = W[(size_t)(2 * k2) * 256 + n];
    float hi = W[(size_t)(2 * k2 + 1) * 256 + n];
    bf162 p = __floats2bfloat162_rn(lo, hi);     // x = even k (low 16 bits)
    wp[(size_t)m * 32768 + i] = *(uint32_t*)&p;
}

__global__ void __launch_bounds__(256) conv_f32_bf16(
    const float* __restrict__ in, bf16* __restrict__ out, int n4)
{
    int i = blockIdx.x * blockDim.x + threadIdx.x;
    if (i >= n4) return;
    float4 v = ((const float4*)in)[i];
    bf162 a = __floats2bfloat162_rn(v.x, v.y);
    bf162 b = __floats2bfloat162_rn(v.z, v.w);
    uint2 u;
    u.x = *(uint32_t*)&a;
    u.y = *(uint32_t*)&b;
    ((uint2*)out)[i] = u;
}

// ---------------------------------------------------------------------------
// bf16 GEMM: C[N,256](bf16) = A[N,256](bf16) @ W(prepacked)  (+ epilogue)
// EPI 0: plain. EPI 1: elu(acc+bias). EPI 2: (acc+bias)*extra(bf16)
// 128x128 tile, BK=32, 2-stage cp.async, 8 warps (4Mx2N), m16n8k16.
// ---------------------------------------------------------------------------
#define ASB   40     // bf16 stride (32 + 8 pad) -> 80B rows, conflict-free
#define BSPW  136    // uint32 stride (128 + 8 pad) -> conflict-free

template <int EPI>
__global__ void __launch_bounds__(256) bf16_gemm(
    const bf16* __restrict__ A, const uint32_t* __restrict__ Wp,
    const float* __restrict__ bias, const bf16* __restrict__ extra,
    bf16* __restrict__ C, int N)
{
    __shared__ __align__(16) bf16     As[2][128 * ASB];
    __shared__ __align__(16) uint32_t Bsp[2][16 * BSPW];

    const int tid  = threadIdx.x;
    const int lane = tid & 31;
    const int wid  = tid >> 5;
    const int wm   = wid & 3;
    const int wn   = wid >> 2;
    const int rowBase = blockIdx.x * 128;
    const int colBase = blockIdx.y * 128;
    const int lq = lane >> 2;    // group 0..7
    const int lr = lane & 3;     // 0..3

    float acc[2][8][4];
#pragma unroll
    for (int mt = 0; mt < 2; mt++)
#pragma unroll
        for (int nt = 0; nt < 8; nt++)
#pragma unroll
            for (int i = 0; i < 4; i++) acc[mt][nt][i] = 0.f;

    auto loadTile = [&](int k0, int st) {
#pragma unroll
        for (int i = 0; i < 2; i++) {
            int ch = tid + i * 256;           // 0..511
            int r  = ch >> 2;                 // 0..127
            int kc = (ch & 3) * 8;            // bf16 offset 0,8,16,24
            int grow = rowBase + r;
            int ok = (grow < N) ? 16 : 0;
            int crow = (grow < N) ? grow : (N - 1);
            cp_async16(&As[st][r * ASB + kc], A + (size_t)crow * 256 + k0 + kc, ok);
        }
#pragma unroll
        for (int i = 0; i < 2; i++) {
            int ch = tid + i * 256;
            int k2 = ch >> 5;                 // 0..15
            int nc = (ch & 31) * 4;           // 0..124
            cp_async16(&Bsp[st][k2 * BSPW + nc],
                       Wp + (size_t)(k0 / 2 + k2) * 256 + colBase + nc, 16);
        }
        asm volatile("cp.async.commit_group;");
    };

    loadTile(0, 0);
#pragma unroll
    for (int it = 0; it < 8; it++) {
        if (it < 7) {
            loadTile((it + 1) * 32, (it + 1) & 1);
            asm volatile("cp.async.wait_group 1;");
        } else {
            asm volatile("cp.async.wait_group 0;");
        }
        __syncthreads();
        const bf16* As_ = As[it & 1];
        const uint32_t* Bp = Bsp[it & 1];
#pragma unroll
        for (int ks = 0; ks < 2; ks++) {          // two k16 steps per BK=32
            uint32_t a[2][4];
#pragma unroll
            for (int mt = 0; mt < 2; mt++) {
                int r = wm * 32 + mt * 16 + lq;
                const uint32_t* ar0 = (const uint32_t*)(As_ + r * ASB) + ks * 8 + lr;
                const uint32_t* ar1 = (const uint32_t*)(As_ + (r + 8) * ASB) + ks * 8 + lr;
                a[mt][0] = ar0[0];
                a[mt][1] = ar1[0];
                a[mt][2] = ar0[4];
                a[mt][3] = ar1[4];
            }
            uint32_t b0[8], b1[8];
#pragma unroll
            for (int nt = 0; nt < 8; nt++) {
                int n = wn * 64 + nt * 8 + lq;
                b0[nt] = Bp[(ks * 8 + lr) * BSPW + n];
                b1[nt] = Bp[(ks * 8 + lr + 4) * BSPW + n];
            }
#pragma unroll
            for (int mt = 0; mt < 2; mt++)
#pragma unroll
                for (int nt = 0; nt < 8; nt++)
                    mma_bf16(acc[mt][nt][0], acc[mt][nt][1], acc[mt][nt][2], acc[mt][nt][3],
                             a[mt][0], a[mt][1], a[mt][2], a[mt][3], b0[nt], b1[nt]);
        }
        __syncthreads();
    }

    // --- epilogue (bf16 out) ---
#pragma unroll
    for (int mt = 0; mt < 2; mt++) {
#pragma unroll
        for (int rr = 0; rr < 2; rr++) {
            int row = rowBase + wm * 32 + mt * 16 + lq + rr * 8;
            if (row >= N) continue;
#pragma unroll
            for (int nt = 0; nt < 8; nt++) {
                int col = colBase + wn * 64 + nt * 8 + 2 * lr;
                float v0 = acc[mt][nt][rr * 2 + 0];
                float v1 = acc[mt][nt][rr * 2 + 1];
                if (EPI >= 1) { v0 += bias[col]; v1 += bias[col + 1]; }
                if (EPI == 1) {
                    v0 = v0 > 0.f ? v0 : expm1f(v0);
                    v1 = v1 > 0.f ? v1 : expm1f(v1);
                }
                if (EPI == 2) {
                    float2 ex = __bfloat1622float2(
                        *(const bf162*)(extra + (size_t)row * 256 + col));
                    v0 *= ex.x; v1 *= ex.y;
                }
                *(bf162*)(C + (size_t)row * 256 + col) = __floats2bfloat162_rn(v0, v1);
            }
        }
    }
}

// ---------------------------------------------------------------------------
// CSR build
// ---------------------------------------------------------------------------
__global__ void count_deg(const int* __restrict__ dst, int* __restrict__ degi, int E) {
    int e = blockIdx.x * blockDim.x + threadIdx.x;
    if (e < E) atomicAdd(&degi[dst[e]], 1);
}

__global__ void finalize_deg(const int* __restrict__ degi, float* __restrict__ dinv,
                             float* __restrict__ invdeg, int N) {
    int i = blockIdx.x * blockDim.x + threadIdx.x;
    if (i < N) {
        float d = (float)degi[i] + 1.f;
        dinv[i] = rsqrtf(d);
        invdeg[i] = 1.f / d;
    }
}

__global__ void __launch_bounds__(1024) scan_rowptr(
    const int* __restrict__ degi, int* __restrict__ rowptr, int N)
{
    __shared__ int s[1024];
    const int t = threadIdx.x;
    const int per = (N + 1023) / 1024;
    const int beg = t * per;
    const int end = min(beg + per, N);
    int sum = 0;
    for (int i = beg; i < end; i++) sum += degi[i];
    s[t] = sum;
    __syncthreads();
#pragma unroll
    for (int off = 1; off < 1024; off <<= 1) {
        int v = (t >= off) ? s[t - off] : 0;
        __syncthreads();
        s[t] += v;
        __syncthreads();
    }
    int run = s[t] - sum;
    for (int i = beg; i < end; i++) { rowptr[i] = run; run += degi[i]; }
    if (t == 1023) rowptr[N] = s[1023];
}

__global__ void fill_csr(const int* __restrict__ src, const int* __restrict__ dst,
                         const float* __restrict__ dinv,
                         const int* __restrict__ rowptr, int* __restrict__ cursor,
                         int* __restrict__ csrsrc, float* __restrict__ coef, int E)
{
    int e = blockIdx.x * blockDim.x + threadIdx.x;
    if (e >= E) return;
    int s = src[e], d = dst[e];
    int p = atomicAdd(&cursor[d], 1);
    int slot = rowptr[d] + p;
    csrsrc[slot] = s;
    coef[slot] = dinv[s] * dinv[d];
}

// ---------------------------------------------------------------------------
// Gather SpMM (bf16 in/out) + fused combine. 1 warp per destination row.
// ---------------------------------------------------------------------------
__device__ __forceinline__ void accum8(float* acc, uint4 v, float c) {
    bf162* p = (bf162*)&v;
#pragma unroll
    for (int j = 0; j < 4; j++) {
        float2 f = __bfloat1622float2(p[j]);
        acc[2 * j]     += f.x * c;
        acc[2 * j + 1] += f.y * c;
    }
}

template <int RES, int SCALE, int ELU>
__global__ void __launch_bounds__(256) gather_gcn_bf16(
    const bf16* __restrict__ h, const int* __restrict__ rowptr,
    const int* __restrict__ csrsrc, const float* __restrict__ coef,
    const float* __restrict__ bias, const float* __restrict__ invdeg,
    const bf16* __restrict__ res, const float* __restrict__ scale_ptr,
    bf16* __restrict__ out, int N)
{
    int d = (blockIdx.x * blockDim.x + threadIdx.x) >> 5;
    int lane = threadIdx.x & 31;
    if (d >= N) return;

    const int eBeg = rowptr[d];
    const int eEnd = rowptr[d + 1];
    const int coff = lane * 8;

    float acc[8] = {0.f, 0.f, 0.f, 0.f, 0.f, 0.f, 0.f, 0.f};

    int e = eBeg;
    for (; e + 1 < eEnd; e += 2) {
        int s0 = csrsrc[e];     float c0 = coef[e];
        int s1 = csrsrc[e + 1]; float c1 = coef[e + 1];
        uint4 v0 = *(const uint4*)(h + (size_t)s0 * DD + coff);
        uint4 v1 = *(const uint4*)(h + (size_t)s1 * DD + coff);
        accum8(acc, v0, c0);
        accum8(acc, v1, c1);
    }
    if (e < eEnd) {
        int s0 = csrsrc[e]; float c0 = coef[e];
        uint4 v0 = *(const uint4*)(h + (size_t)s0 * DD + coff);
        accum8(acc, v0, c0);
    }

    uint4 vs = *(const uint4*)(h + (size_t)d * DD + coff);
    accum8(acc, vs, invdeg[d]);
    float4 b0 = ((const float4*)bias)[lane * 2];
    float4 b1 = ((const float4*)bias)[lane * 2 + 1];
    acc[0] += b0.x; acc[1] += b0.y; acc[2] += b0.z; acc[3] += b0.w;
    acc[4] += b1.x; acc[5] += b1.y; acc[6] += b1.z; acc[7] += b1.w;

    if (RES) {
        uint4 rv = *(const uint4*)(res + (size_t)d * DD + coff);
        accum8(acc, rv, 1.f);
    }
    if (SCALE) {
        float sc = scale_ptr[0];
#pragma unroll
        for (int j = 0; j < 8; j++) acc[j] *= sc;
    }
    if (ELU) {
#pragma unroll
        for (int j = 0; j < 8; j++) acc[j] = acc[j] > 0.f ? acc[j] : expm1f(acc[j]);
    }
    uint4 ov;
    bf162* op = (bf162*)&ov;
#pragma unroll
    for (int j = 0; j < 4; j++) op[j] = __floats2bfloat162_rn(acc[2 * j], acc[2 * j + 1]);
    *(uint4*)(out + (size_t)d * DD + coff) = ov;
}

// ---------------------------------------------------------------------------
// Prompt attention on the M selected rows (bf16 h). 1 warp / row.
// ---------------------------------------------------------------------------
__global__ void __launch_bounds__(256) embed_select(
    const bf16* __restrict__ h, const float* __restrict__ aW,
    const float* __restrict__ ab, const float* __restrict__ p,
    const int* __restrict__ idx, float* __restrict__ raw, int M)
{
    int m = (blockIdx.x * blockDim.x + threadIdx.x) >> 5;
    int lane = threadIdx.x & 31;
    if (m >= M) return;
    int node = idx[m];
    const bf16* hr = h + (size_t)node * DD;
    float hv[8];
    float lg[5] = {0.f, 0.f, 0.f, 0.f, 0.f};
#pragma unroll
    for (int i = 0; i < 8; i++) {
        int c = lane + 32 * i;
        hv[i] = __bfloat162float(hr[c]);
#pragma unroll
        for (int k = 0; k < 5; k++) lg[k] += hv[i] * aW[c * 5 + k];
    }
#pragma unroll
    for (int k = 0; k < 5; k++) lg[k] = warp_sum(lg[k]) + ab[k];
    float mx = lg[0];
#pragma unroll
    for (int k = 1; k < 5; k++) mx = fmaxf(mx, lg[k]);
    float wgt[5], s = 0.f;
#pragma unroll
    for (int k = 0; k < 5; k++) { wgt[k] = expf(lg[k] - mx); s += wgt[k]; }
    float inv = 1.f / s;
#pragma unroll
    for (int k = 0; k < 5; k++) wgt[k] *= inv;
#pragma unroll
    for (int i = 0; i < 8; i++) {
        int c = lane + 32 * i;
        float v = hv[i];
#pragma unroll
        for (int k = 0; k < 5; k++) v += wgt[k] * p[k * DD + c];
        raw[(size_t)m * DD + c] = v;
    }
}

// ---------------------------------------------------------------------------
// Class prototypes + cosine softmax
// ---------------------------------------------------------------------------
__global__ void __launch_bounds__(256) proto_accum(
    const float* __restrict__ raw, const int* __restrict__ labels,
    float* __restrict__ sums, float* __restrict__ cnt, int M)
{
    int m = (blockIdx.x * blockDim.x + threadIdx.x) >> 5;
    int lane = threadIdx.x & 31;
    if (m >= M) return;
    int lab = labels[m];
#pragma unroll
    for (int i = 0; i < 8; i++) {
        int c = lane + 32 * i;
        atomicAdd(&g_sums[lab * DD + c], raw[(size_t)m * DD + c]);
    }
    if (lane == 0) atomicAdd(&g_sums[NC * DD + lab], 1.f);
}

__global__ void an_finalize(const float* __restrict__ sums,
                            const float* __restrict__ cnt, float* __restrict__ an)
{
    int c = blockIdx.x;
    int lane = threadIdx.x;
    float invc = 1.f / fmaxf(cnt[c], 1.f);
    float v[8];
    float ss = 0.f;
#pragma unroll
    for (int i = 0; i < 8; i++) {
        v[i] = sums[c * DD + lane + 32 * i] * invc;
        ss += v[i] * v[i];
    }
    ss = warp_sum(ss);
    float innorm = 1.f / fmaxf(sqrtf(ss), 1e-8f);
#pragma unroll
    for (int i = 0; i < 8; i++) an[c * DD + lane + 32 * i] = v[i] * innorm;
}

__global__ void __launch_bounds__(256) cos_softmax(
    const float* __restrict__ raw, const float* __restrict__ an,
    float* __restrict__ out, int M)
{
    __shared__ float sAn[NC * DD];
    for (int i = threadIdx.x; i < NC * DD; i += 256) sAn[i] = an[i];
    __syncthreads();
    int m = (blockIdx.x * blockDim.x + threadIdx.x) >> 5;
    int lane = threadIdx.x & 31;
    if (m >= M) return;
    float rv[8];
    float ss = 0.f;
#pragma unroll
    for (int i = 0; i < 8; i++) {
        rv[i] = raw[(size_t)m * DD + lane + 32 * i];
        ss += rv[i] * rv[i];
    }
    ss = warp_sum(ss);
    float rinv = 1.f / fmaxf(sqrtf(ss), 1e-8f);
    float sim[NC];
#pragma unroll
    for (int c = 0; c < NC; c++) {
        float s = 0.f;
#pragma unroll
        for (int i = 0; i < 8; i++) s += rv[i] * sAn[c * DD + lane + 32 * i];
        sim[c] = warp_sum(s) * rinv;
    }
    if (lane == 0) {
        float mx = sim[0];
#pragma unroll
        for (int c = 1; c < NC; c++) mx = fmaxf(mx, sim[c]);
        float e[NC], s = 0.f;
#pragma unroll
        for (int c = 0; c < NC; c++) { e[c] = expf(sim[c] - mx); s += e[c]; }
        float inv = 1.f / s;
#pragma unroll
        for (int c = 0; c < NC; c++) out[(size_t)m * NC + c] = e[c] * inv;
    }
}

// ---------------------------------------------------------------------------
// Orchestration
// ---------------------------------------------------------------------------
extern "C" void kernel_launch(void* const* d_in, const int* in_sizes, int n_in,
                              void* d_out, int out_size)
{
    const float* x0     = (const float*)d_in[0];
    const int*   src    = (const int*)d_in[1];
    const int*   dst    = (const int*)d_in[2];
    const int*   idx    = (const int*)d_in[3];
    const int*   labels = (const int*)d_in[4];
    const float* W1 = (const float*)d_in[6];
    const float* b1 = (const float*)d_in[7];
    const float* W2 = (const float*)d_in[8];
    const float* b2 = (const float*)d_in[9];
    const float* W3 = (const float*)d_in[10];
    const float* b3 = (const float*)d_in[11];
    const float* cw_in  = (const float*)d_in[12];
    const float* cb_in  = (const float*)d_in[13];
    const float* cw_hid = (const float*)d_in[14];
    const float* cb_hid = (const float*)d_in[15];
    const float* cw_out = (const float*)d_in[16];
    const float* cb_out = (const float*)d_in[17];
    const float* p_list = (const float*)d_in[18];
    const float* aW     = (const float*)d_in[19];
    const float* ab     = (const float*)d_in[20];
    const float* gw2    = (const float*)d_in[21];

    const int N = in_sizes[0] / DD;
    const int E = in_sizes[1];
    const int M = in_sizes[3];
    float* out = (float*)d_out;

    bf16 *bxb, *bx0b, *bhb, *be1b, *be2b;
    float *bdinv, *binvdeg, *braw, *bsums, *ban, *bcoef;
    uint32_t* bwp;
    int *bdegi, *browptr, *bcursor, *bcsrsrc;
    cudaGetSymbolAddress((void**)&bxb,  g_xb);
    cudaGetSymbolAddress((void**)&bx0b, g_x0b);
    cudaGetSymbolAddress((void**)&bhb,  g_hb);
    cudaGetSymbolAddress((void**)&be1b, g_e1b);
    cudaGetSymbolAddress((void**)&be2b, g_e2b);
    cudaGetSymbolAddress((void**)&bwp,  g_wp);
    cudaGetSymbolAddress((void**)&bdegi, g_degi);
    cudaGetSymbolAddress((void**)&bdinv, g_dinv);
    cudaGetSymbolAddress((void**)&binvdeg, g_invdeg);
    cudaGetSymbolAddress((void**)&browptr, g_rowptr);
    cudaGetSymbolAddress((void**)&bcursor, g_cursor);
    cudaGetSymbolAddress((void**)&bcsrsrc, g_csrsrc);
    cudaGetSymbolAddress((void**)&bcoef, g_coef);
    cudaGetSymbolAddress((void**)&braw, g_raw);
    cudaGetSymbolAddress((void**)&bsums, g_sums);
    cudaGetSymbolAddress((void**)&ban, g_an);
    float* bcnt = bsums + NC * DD;

    // --- prepack weights + convert x0 ---
    prepack_weights<<<dim3(128, 12), 256>>>(W1, W2, W3, cw_in, cw_hid, cw_out, bwp);
    {
        int n4 = N * DD / 4;
        conv_f32_bf16<<<(n4 + 255) / 256, 256>>>(x0, bx0b, n4);
    }

    // --- CSR build ---
    cudaMemsetAsync(bdegi, 0, (size_t)N * sizeof(int), 0);
    cudaMemsetAsync(bcursor, 0, (size_t)N * sizeof(int), 0);
    count_deg<<<(E + 255) / 256, 256>>>(dst, bdegi, E);
    finalize_deg<<<(N + 255) / 256, 256>>>(bdegi, bdinv, binvdeg, N);
    scan_rowptr<<<1, 1024>>>(bdegi, browptr, N);
    fill_csr<<<(E + 255) / 256, 256>>>(src, dst, bdinv, browptr, bcursor, bcsrsrc, bcoef, E);

    const dim3 gg((N + 127) / 128, 2);
    const int rowBlocks = (N + 7) / 8;
    const uint32_t* wp1 = bwp;
    const uint32_t* wp2 = bwp + 1 * 32768;
    const uint32_t* wp3 = bwp + 2 * 32768;

    const bf16* cur = bx0b;
    for (int t = 0; t < 3; t++) {
        bf16_gemm<0><<<gg, 256>>>(cur, wp1, nullptr, nullptr, bhb, N);
        gather_gcn_bf16<0, 0, 0><<<rowBlocks, 256>>>(bhb, browptr, bcsrsrc, bcoef, b1, binvdeg,
                                                     nullptr, nullptr, be1b, N);
        bf16_gemm<0><<<gg, 256>>>(be1b, wp2, nullptr, nullptr, bhb, N);
        gather_gcn_bf16<1, 1, 0><<<rowBlocks, 256>>>(bhb, browptr, bcsrsrc, bcoef, b2, binvdeg,
                                                     be1b, gw2, be2b, N);
        bf16_gemm<1><<<gg, 256>>>(be2b, bwp + (size_t)(3 + t) * 32768, cb_in + t * DD,
                                  nullptr, bhb, N);
        bf16_gemm<1><<<gg, 256>>>(bhb, bwp + (size_t)(6 + t) * 32768, cb_hid + t * DD,
                                  nullptr, be1b, N);
        bf16_gemm<2><<<gg, 256>>>(be1b, bwp + (size_t)(9 + t) * 32768, cb_out + t * DD,
                                  bx0b, bxb, N);
        cur = bxb;
    }

    bf16_gemm<0><<<gg, 256>>>(bxb, wp1, nullptr, nullptr, bhb, N);
    gather_gcn_bf16<0, 0, 1><<<rowBlocks, 256>>>(bhb, browptr, bcsrsrc, bcoef, b1, binvdeg,
                                                 nullptr, nullptr, be1b, N);
    bf16_gemm<0><<<gg, 256>>>(be1b, wp2, nullptr, nullptr, bhb, N);
    gather_gcn_bf16<0, 0, 1><<<rowBlocks, 256>>>(bhb, browptr, bcsrsrc, bcoef, b2, binvdeg,
                                                 nullptr, nullptr, be2b, N);
    bf16_gemm<0><<<gg, 256>>>(be2b, wp3, nullptr, nullptr, bhb, N);
    gather_gcn_bf16<0, 0, 1><<<rowBlocks, 256>>>(bhb, browptr, bcsrsrc, bcoef, b3, binvdeg,
                                                 nullptr, nullptr, be1b, N);

    embed_select<<<(M + 7) / 8, 256>>>(be1b, aW, ab, p_list, idx, braw, M);

    cudaMemsetAsync(bsums, 0, (NC * DD + 32) * sizeof(float), 0);
    proto_accum<<<(M + 7) / 8, 256>>>(braw, labels, bsums, bcnt, M);
    an_finalize<<<NC, 32>>>(bsums, bcnt, ban);
    cos_softmax<<<(M + 7) / 8, 256>>>(braw, ban, out, M);
}